// round 6
// baseline (speedup 1.0000x reference)
#include <cuda_runtime.h>
#include <cstdint>
#include <cstddef>

// ---------------------------------------------------------------------------
// Problem constants
// ---------------------------------------------------------------------------
#define NB   8
#define NH   4
#define SEQ  2048
#define DM   64

// attention tiling
#define TQ   64          // q rows per CTA
#define KSTR 132         // K tile row stride (floats)
#define VSTR 72
#define PSTR 68

// ---------------------------------------------------------------------------
// Static device scratch
// ---------------------------------------------------------------------------
__device__ float    g_gates[3 * NB];
__device__ int      g_mask_mode;                           // 1 = int32 mask, 0 = byte mask
__device__ float    g_Qe[(size_t)NB * NH * SEQ * 128];     // 33.5 MB
__device__ float    g_Ke[(size_t)NB * NH * SEQ * 128];     // 33.5 MB
__device__ float    g_Ve[(size_t)NB * NH * SEQ * 64];      // 16.8 MB
__device__ float    g_ctx[(size_t)NB * SEQ * 256];         // 16.8 MB
__device__ unsigned g_maskb[(size_t)NB * SEQ * 64];        // 4 MB  (bit-packed mask)
__device__ float    g_inv[(size_t)NB * NH * SEQ];          // per-row 1/sum

// ---------------------------------------------------------------------------
// Helpers
// ---------------------------------------------------------------------------
__device__ __forceinline__ float tf32r(float x) {
    float y;
    asm("cvt.rna.tf32.f32 %0, %1;" : "=f"(y) : "f"(x));
    return y;
}

__device__ __forceinline__ void mma_tf32(float& c0, float& c1, float& c2, float& c3,
                                         unsigned a0, unsigned a1, unsigned a2, unsigned a3,
                                         unsigned b0, unsigned b1) {
    asm volatile(
        "mma.sync.aligned.m16n8k8.row.col.f32.tf32.tf32.f32 "
        "{%0,%1,%2,%3},{%4,%5,%6,%7},{%8,%9},{%0,%1,%2,%3};"
        : "+f"(c0), "+f"(c1), "+f"(c2), "+f"(c3)
        : "r"(a0), "r"(a1), "r"(a2), "r"(a3), "r"(b0), "r"(b1));
}

__device__ __forceinline__ void cp_async16(void* smem, const void* gmem) {
    unsigned sa = (unsigned)__cvta_generic_to_shared(smem);
    asm volatile("cp.async.cg.shared.global [%0], [%1], 16;\n" :: "r"(sa), "l"(gmem));
}
__device__ __forceinline__ void cp_async4(void* smem, const void* gmem) {
    unsigned sa = (unsigned)__cvta_generic_to_shared(smem);
    asm volatile("cp.async.ca.shared.global [%0], [%1], 4;\n" :: "r"(sa), "l"(gmem));
}
#define CP_COMMIT() asm volatile("cp.async.commit_group;\n")
#define CP_WAIT(n)  asm volatile("cp.async.wait_group %0;\n" :: "n"(n))

// ---------------------------------------------------------------------------
// Kernel D: detect mask encoding (int32 vs byte)
// ---------------------------------------------------------------------------
__global__ void detect_mask_kernel(const unsigned char* __restrict__ m) {
    int found = 0;
    for (int i = threadIdx.x; i < 1024; i += 32)
        if (m[i * 4 + 1] | m[i * 4 + 2] | m[i * 4 + 3]) found = 1;
    for (int o = 16; o; o >>= 1)
        found |= __shfl_xor_sync(0xffffffffu, found, o);
    if (threadIdx.x == 0) g_mask_mode = found ? 0 : 1;
}

// ---------------------------------------------------------------------------
// Kernel M: bit-pack the mask, ballot-based (fully coalesced).
// One thread per mask element; lane 0 of each warp writes one u32 word.
// ---------------------------------------------------------------------------
__global__ void __launch_bounds__(256) convert_mask_kernel(const void* __restrict__ mask) {
    unsigned gid = blockIdx.x * 256 + threadIdx.x;     // over NB*SEQ*SEQ = 33.5M
    unsigned nz;
    if (g_mask_mode) nz = (((const int*)mask)[gid] != 0) ? 1u : 0u;
    else             nz = (((const unsigned char*)mask)[gid] != 0) ? 1u : 0u;
    unsigned bits = __ballot_sync(0xffffffffu, nz);
    if ((threadIdx.x & 31) == 0) g_maskb[gid >> 5] = bits;
}

// ---------------------------------------------------------------------------
// Kernel 0: scalar gates
// ---------------------------------------------------------------------------
__global__ void gates_kernel(const float* __restrict__ u,
                             const float* __restrict__ sq1, const float* __restrict__ sq2,
                             const float* __restrict__ sk1, const float* __restrict__ sk2,
                             const float* __restrict__ sv1, const float* __restrict__ sv2) {
    const int b = blockIdx.x;
    const int lane = threadIdx.x;
    float hq = 0.f, hk = 0.f, hv = 0.f;
    for (int d = 0; d < DM; ++d) {
        float uv = u[b * DM + d];
        hq += uv * sq1[d * 32 + lane];
        hk += uv * sk1[d * 32 + lane];
        hv += uv * sv1[d * 32 + lane];
    }
    hq = fmaxf(hq, 0.f) * sq2[lane];
    hk = fmaxf(hk, 0.f) * sk2[lane];
    hv = fmaxf(hv, 0.f) * sv2[lane];
    for (int off = 16; off; off >>= 1) {
        hq += __shfl_xor_sync(0xffffffffu, hq, off);
        hk += __shfl_xor_sync(0xffffffffu, hk, off);
        hv += __shfl_xor_sync(0xffffffffu, hv, off);
    }
    if (lane == 0) {
        g_gates[b]      = hq;
        g_gates[8 + b]  = hk;
        g_gates[16 + b] = hv;
    }
}

// ---------------------------------------------------------------------------
// Kernel 1 (v2): projections, register-tiled, weights via __ldg (L1-resident).
// 32 rows per CTA, 256 threads, grid 512. smem: xs 32x68 + uo 3x(32x68).
// ---------------------------------------------------------------------------
#define PROJ_SMEM_BYTES ((32*68 + 3*32*68) * 4)

__global__ void __launch_bounds__(256) proj_kernel(
    const float* __restrict__ x,
    const float* __restrict__ wq, const float* __restrict__ wk, const float* __restrict__ wv,
    const float* __restrict__ uqw, const float* __restrict__ ukw, const float* __restrict__ uvw) {
    extern __shared__ float sm[];
    float* xs = sm;               // 32 x 68
    float* uo = xs + 32 * 68;     // 3 x (32 x 68), plane stride 2176

    const int t = threadIdx.x;
    const int row0 = blockIdx.x * 32;
    const int b    = row0 >> 11;
    const int lr0  = row0 & (SEQ - 1);

    for (int i = t; i < 32 * 16; i += 256) {
        int r = i >> 4, c = (i & 15) * 4;
        *(float4*)(xs + r * 68 + c) = *(const float4*)(x + (size_t)(row0 + r) * DM + c);
    }
    __syncthreads();

    const int rg = t >> 5;     // 8 groups x 4 rows
    const int cg = t & 31;

    // u projections (192 output cols): mat = cg>>3, cols (cg&7)*8
    if (cg < 24) {
        const int mat = cg >> 3;
        const int c0 = (cg & 7) * 8;
        const float* w = (mat == 0) ? uqw : (mat == 1) ? ukw : uvw;
        float acc[4][8];
        #pragma unroll
        for (int i = 0; i < 4; ++i)
            #pragma unroll
            for (int j = 0; j < 8; ++j) acc[i][j] = 0.f;
        for (int k = 0; k < 64; ++k) {
            float av[4];
            #pragma unroll
            for (int i = 0; i < 4; ++i) av[i] = xs[(rg * 4 + i) * 68 + k];
            float4 b0 = __ldg((const float4*)(w + k * 64 + c0));
            float4 b1 = __ldg((const float4*)(w + k * 64 + c0 + 4));
            float bv[8] = {b0.x, b0.y, b0.z, b0.w, b1.x, b1.y, b1.z, b1.w};
            #pragma unroll
            for (int i = 0; i < 4; ++i)
                #pragma unroll
                for (int j = 0; j < 8; ++j) acc[i][j] += av[i] * bv[j];
        }
        float* dst = uo + mat * 2176;
        #pragma unroll
        for (int i = 0; i < 4; ++i)
            #pragma unroll
            for (int j = 0; j < 8; ++j)
                dst[(rg * 4 + i) * 68 + c0 + j] = acc[i][j];
    }
    __syncthreads();

    const float gq = g_gates[b] * 0.125f;
    const float gk = g_gates[8 + b];
    const float gv = g_gates[16 + b];

    // u-halves of Qe / Ke (same for all 4 heads)
    for (int i = t; i < 32 * 64; i += 256) {
        int r = i >> 6, j = i & 63;
        float vq = tf32r(uo[r * 68 + j] * gq);
        float vk = tf32r(uo[2176 + r * 68 + j] * gk);
        size_t l = lr0 + r;
        #pragma unroll
        for (int h = 0; h < 4; ++h) {
            size_t base = (((size_t)b * 4 + h) * SEQ + l) * 128 + 64 + j;
            g_Qe[base] = vq;
            g_Ke[base] = vk;
        }
    }

    // big GEMMs: Q, K, V with weights streamed from L1
    for (int m = 0; m < 3; ++m) {
        const float* w = (m == 0) ? wq : (m == 1) ? wk : wv;
        float acc[4][8];
        #pragma unroll
        for (int i = 0; i < 4; ++i)
            #pragma unroll
            for (int j = 0; j < 8; ++j) acc[i][j] = 0.f;
        for (int k = 0; k < 64; ++k) {
            float av[4];
            #pragma unroll
            for (int i = 0; i < 4; ++i) av[i] = xs[(rg * 4 + i) * 68 + k];
            float4 b0 = __ldg((const float4*)(w + k * 256 + cg * 8));
            float4 b1 = __ldg((const float4*)(w + k * 256 + cg * 8 + 4));
            float bv[8] = {b0.x, b0.y, b0.z, b0.w, b1.x, b1.y, b1.z, b1.w};
            #pragma unroll
            for (int i = 0; i < 4; ++i)
                #pragma unroll
                for (int j = 0; j < 8; ++j) acc[i][j] += av[i] * bv[j];
        }

        const int c0 = cg * 8;
        const int h  = c0 >> 6;
        const int j0 = c0 & 63;
        if (m == 2) {
            #pragma unroll
            for (int i = 0; i < 4; ++i) {
                size_t l = lr0 + rg * 4 + i;
                size_t base = (((size_t)b * 4 + h) * SEQ + l) * 64 + j0;
                #pragma unroll
                for (int j = 0; j < 8; ++j)
                    g_Ve[base + j] = acc[i][j] + uo[2 * 2176 + (rg * 4 + i) * 68 + j0 + j] * gv;
            }
        } else {
            float* tgt = (m == 0) ? g_Qe : g_Ke;
            float s = (m == 0) ? 0.125f : 1.0f;
            #pragma unroll
            for (int i = 0; i < 4; ++i) {
                size_t l = lr0 + rg * 4 + i;
                size_t base = (((size_t)b * 4 + h) * SEQ + l) * 128 + j0;
                #pragma unroll
                for (int j = 0; j < 8; ++j)
                    tgt[base + j] = tf32r(acc[i][j] * s);
            }
        }
    }
}

// ---------------------------------------------------------------------------
// Kernel 2 (v3): attention. CTA = (b,h, 64 q-rows), 1024 threads / 32 warps.
// Race-free double-buffered cp.async pipeline: prefetch is issued only after
// the mid-tile sync (so every warp has left the buffer being overwritten).
// Warp layout: qh = w>>3 (16-row quarter), n0 = (w&7)*8 (k-col group).
// ---------------------------------------------------------------------------
#define ATT_SMEM_FLOATS (TQ*KSTR + 2*64*KSTR + 2*64*VSTR + TQ*PSTR + 512 + 64 + 256)
#define ATT_SMEM_BYTES  (ATT_SMEM_FLOATS * 4)

__global__ void __launch_bounds__(1024, 1) attn2_kernel(float* __restrict__ attn_out) {
    extern __shared__ float sm[];
    float* qs  = sm;                       // 64 x 132
    float* ks  = qs + TQ * KSTR;           // 2 x 64 x 132
    float* vs  = ks + 2 * 64 * KSTR;       // 2 x 64 x 72
    float* ps  = vs + 2 * 64 * VSTR;       // 64 x 68
    float* red = ps + TQ * PSTR;           // 32 x 16
    float* inv = red + 512;                // 64
    unsigned* msb = (unsigned*)(inv + 64); // 2 x 128

    const int t    = threadIdx.x;
    const int w    = t >> 5;
    const int lane = t & 31;
    const int g    = lane >> 2;
    const int tig  = lane & 3;
    const int qh   = w >> 3;               // 0..3: 16-row quarter
    const int n0   = (w & 7) * 8;          // k-col group within tile
    const int ra   = qh * 16 + g;          // mma row a
    const int rb   = qh * 16 + 8 + g;      // mma row b

    const int bh = blockIdx.x >> 5;        // 32 q-tiles per (b,h)
    const int qt = blockIdx.x & 31;
    const int b  = bh >> 2;
    const int h  = bh & 3;
    const int q0 = qt * TQ;

    const float* Qg = g_Qe + ((size_t)bh * SEQ + q0) * 128;
    const float* Kg = g_Ke + (size_t)bh * SEQ * 128;
    const float* Vg = g_Ve + (size_t)bh * SEQ * 64;
    const unsigned* Mb = g_maskb + ((size_t)b * SEQ + q0) * 64;
    float* ao = attn_out + ((size_t)bh * SEQ + q0) * SEQ;

    // ---- stage Q + tile 0 ----
    for (int i = t; i < TQ * 32; i += 1024) {
        int r = i >> 5, c = (i & 31) * 4;
        cp_async16(qs + r * KSTR + c, Qg + (size_t)r * 128 + c);
    }
    for (int i = t; i < 64 * 32; i += 1024) {
        int r = i >> 5, c = (i & 31) * 4;
        cp_async16(ks + r * KSTR + c, Kg + (size_t)r * 128 + c);
    }
    for (int i = t; i < 64 * 16; i += 1024) {
        int r = i >> 4, c = (i & 15) * 4;
        cp_async16(vs + r * VSTR + c, Vg + (size_t)r * 64 + c);
    }
    if (t < 2 * TQ)
        cp_async4(msb + t, Mb + (size_t)(t >> 1) * 64 + (t & 1));
    CP_COMMIT();
    CP_WAIT(0);
    __syncthreads();

    float ctx0 = 0.f, ctx1 = 0.f, ctx2 = 0.f, ctx3 = 0.f;
    float sl0 = 0.f, sl1 = 0.f;

    for (int tile = 0; tile < SEQ / 64; ++tile) {
        const int buf = tile & 1;
        const float* kb = ks + buf * 64 * KSTR;
        const float* vb = vs + buf * 64 * VSTR;
        const unsigned* mb = msb + buf * 2 * TQ;
        const int k0 = tile * 64;

        // ---- QK scores (A reloaded from smem; conflict-free) ----
        float c0 = 0.f, c1 = 0.f, c2 = 0.f, c3 = 0.f;
        #pragma unroll
        for (int kk = 0; kk < 16; ++kk) {
            unsigned a0 = __float_as_uint(qs[ra * KSTR + kk * 8 + tig]);
            unsigned a1 = __float_as_uint(qs[rb * KSTR + kk * 8 + tig]);
            unsigned a2 = __float_as_uint(qs[ra * KSTR + kk * 8 + tig + 4]);
            unsigned a3 = __float_as_uint(qs[rb * KSTR + kk * 8 + tig + 4]);
            unsigned b0 = __float_as_uint(kb[(n0 + g) * KSTR + kk * 8 + tig]);
            unsigned b1 = __float_as_uint(kb[(n0 + g) * KSTR + kk * 8 + tig + 4]);
            mma_tf32(c0, c1, c2, c3, a0, a1, a2, a3, b0, b1);
        }

        // ---- mask + exp -> ps (unnormalized), accumulate sums ----
        {
            const int col = n0 + 2 * tig;
            unsigned w0 = mb[ra * 2 + (col >> 5)];
            unsigned w1 = mb[rb * 2 + (col >> 5)];
            float p00 = ((w0 >> (col & 31)) & 1u)       ? 0.f : __expf(c0);
            float p01 = ((w0 >> ((col + 1) & 31)) & 1u) ? 0.f : __expf(c1);
            float p10 = ((w1 >> (col & 31)) & 1u)       ? 0.f : __expf(c2);
            float p11 = ((w1 >> ((col + 1) & 31)) & 1u) ? 0.f : __expf(c3);
            sl0 += p00 + p01;
            sl1 += p10 + p11;
            *(float2*)(ps + ra * PSTR + col) = make_float2(p00, p01);
            *(float2*)(ps + rb * PSTR + col) = make_float2(p10, p11);
        }
        __syncthreads();   // (A) ps complete; all warps past tile-1's buffers

        // ---- prefetch tile+1 into the other buffer (now provably free) ----
        if (tile + 1 < SEQ / 64) {
            const int nb = buf ^ 1;
            const int nk0 = k0 + 64;
            for (int i = t; i < 64 * 32; i += 1024) {
                int r = i >> 5, c = (i & 31) * 4;
                cp_async16(ks + nb * 64 * KSTR + r * KSTR + c,
                           Kg + (size_t)(nk0 + r) * 128 + c);
            }
            for (int i = t; i < 64 * 16; i += 1024) {
                int r = i >> 4, c = (i & 15) * 4;
                cp_async16(vs + nb * 64 * VSTR + r * VSTR + c,
                           Vg + (size_t)(nk0 + r) * 64 + c);
            }
            if (t < 2 * TQ)
                cp_async4(msb + nb * 2 * TQ + t,
                          Mb + (size_t)(t >> 1) * 64 + (nk0 >> 5) + (t & 1));
            CP_COMMIT();
        }

        // ---- write unnormalized p tile to global (coalesced float4) ----
        {
            int r = t >> 4, c4 = (t & 15) * 4;
            *(float4*)(ao + (size_t)r * SEQ + k0 + c4) = *(float4*)(ps + r * PSTR + c4);
        }

        // ---- PV accumulate ----
        #pragma unroll
        for (int kk = 0; kk < 8; ++kk) {
            unsigned pa0 = __float_as_uint(ps[ra * PSTR + kk * 8 + tig]);
            unsigned pa1 = __float_as_uint(ps[rb * PSTR + kk * 8 + tig]);
            unsigned pa2 = __float_as_uint(ps[ra * PSTR + kk * 8 + tig + 4]);
            unsigned pa3 = __float_as_uint(ps[rb * PSTR + kk * 8 + tig + 4]);
            unsigned vb0 = __float_as_uint(vb[(kk * 8 + tig)     * VSTR + n0 + g]);
            unsigned vb1 = __float_as_uint(vb[(kk * 8 + tig + 4) * VSTR + n0 + g]);
            mma_tf32(ctx0, ctx1, ctx2, ctx3, pa0, pa1, pa2, pa3, vb0, vb1);
        }
        CP_WAIT(0);
        __syncthreads();   // (B) prefetched data visible to all; ps free to overwrite
    }

    // ---- row-sum reduction across the 8 n-warps of each quarter ----
    sl0 += __shfl_xor_sync(0xffffffffu, sl0, 1);
    sl0 += __shfl_xor_sync(0xffffffffu, sl0, 2);
    sl1 += __shfl_xor_sync(0xffffffffu, sl1, 1);
    sl1 += __shfl_xor_sync(0xffffffffu, sl1, 2);
    if (tig == 0) {
        red[w * 16 + g]     = sl0;   // row qh*16 + g
        red[w * 16 + 8 + g] = sl1;   // row qh*16 + 8 + g
    }
    __syncthreads();
    if (t < TQ) {
        int qh_r = t >> 4;
        int rr   = t & 15;
        float s = 0.f;
        #pragma unroll
        for (int ww = 0; ww < 8; ++ww) s += red[(qh_r * 8 + ww) * 16 + rr];
        float iv = 1.f / s;
        inv[t] = iv;
        g_inv[(size_t)bh * SEQ + q0 + t] = iv;
    }
    __syncthreads();

    // ---- normalized ctx write ----
    {
        const int col = n0 + 2 * tig;
        float iv0 = inv[ra];
        float iv1 = inv[rb];
        size_t r0 = (size_t)b * SEQ + q0;
        *(float2*)(g_ctx + (r0 + ra) * 256 + h * 64 + col) = make_float2(ctx0 * iv0, ctx1 * iv0);
        *(float2*)(g_ctx + (r0 + rb) * 256 + h * 64 + col) = make_float2(ctx2 * iv1, ctx3 * iv1);
    }
}

// ---------------------------------------------------------------------------
// Kernel 2b: normalize attn rows in place. One block per row.
// ---------------------------------------------------------------------------
__global__ void __launch_bounds__(128) norm_kernel(float* __restrict__ attn) {
    const size_t row = blockIdx.x;
    const float iv = g_inv[row];
    float4* p = (float4*)(attn + row * SEQ);
    #pragma unroll
    for (int i = threadIdx.x; i < SEQ / 4; i += 128) {
        float4 v = p[i];
        v.x *= iv; v.y *= iv; v.z *= iv; v.w *= iv;
        p[i] = v;
    }
}

// ---------------------------------------------------------------------------
// Kernel 3: fc + LN1 + FFN + LN2 (unchanged)
// ---------------------------------------------------------------------------
#define POST_SMEM_BYTES ((64*260 + 256*68 + 4*64*68) * 4)

__global__ void __launch_bounds__(256) post_kernel(
    const float* __restrict__ x, const float* __restrict__ fcw,
    const float* __restrict__ ln1g, const float* __restrict__ ln1b,
    const float* __restrict__ f1, const float* __restrict__ f2,
    const float* __restrict__ ln2g, const float* __restrict__ ln2b,
    float* __restrict__ res) {
    extern __shared__ float sm[];
    float* cs  = sm;                 // 64 x 260
    float* fs  = cs + 64 * 260;      // 256 x 68
    float* hs  = fs + 256 * 68;      // 64 x 68
    float* es  = hs + 64 * 68;       // 64 x 68
    float* f1s = es + 64 * 68;       // 64 x 68
    float* f2s = f1s + 64 * 68;      // 64 x 68

    const int t = threadIdx.x;
    const int row0 = blockIdx.x * 64;

    for (int i = t; i < 64 * 64; i += 256) {
        int r = i >> 6, c = (i & 63) * 4;
        *(float4*)(cs + r * 260 + c) = *(const float4*)(g_ctx + (size_t)(row0 + r) * 256 + c);
    }
    for (int i = t; i < 256 * 16; i += 256) {
        int r = i >> 4, c = (i & 15) * 4;
        *(float4*)(fs + r * 68 + c) = *(const float4*)(fcw + r * 64 + c);
    }
    for (int i = t; i < 64 * 16; i += 256) {
        int r = i >> 4, c = (i & 15) * 4;
        *(float4*)(hs + r * 68 + c)  = *(const float4*)(x + (size_t)(row0 + r) * DM + c);
        *(float4*)(f1s + r * 68 + c) = *(const float4*)(f1 + r * 64 + c);
        *(float4*)(f2s + r * 68 + c) = *(const float4*)(f2 + r * 64 + c);
    }
    __syncthreads();

    const int rg = t >> 4;
    const int cg = t & 15;

    float acc[4][4];
    #pragma unroll
    for (int i = 0; i < 4; ++i)
        #pragma unroll
        for (int j = 0; j < 4; ++j) acc[i][j] = 0.f;
    for (int k = 0; k < 256; ++k) {
        float av[4];
        #pragma unroll
        for (int i = 0; i < 4; ++i) av[i] = cs[(rg * 4 + i) * 260 + k];
        float4 bb = *(const float4*)(fs + k * 68 + cg * 4);
        float bv[4] = {bb.x, bb.y, bb.z, bb.w};
        #pragma unroll
        for (int i = 0; i < 4; ++i)
            #pragma unroll
            for (int j = 0; j < 4; ++j) acc[i][j] += av[i] * bv[j];
    }

    #pragma unroll
    for (int i = 0; i < 4; ++i) {
        float y[4];
        #pragma unroll
        for (int j = 0; j < 4; ++j) y[j] = acc[i][j] + hs[(rg * 4 + i) * 68 + cg * 4 + j];
        float s = y[0] + y[1] + y[2] + y[3];
        float q = y[0]*y[0] + y[1]*y[1] + y[2]*y[2] + y[3]*y[3];
        #pragma unroll
        for (int o = 1; o < 16; o <<= 1) {
            s += __shfl_xor_sync(0xffffffffu, s, o);
            q += __shfl_xor_sync(0xffffffffu, q, o);
        }
        float mu = s * (1.f / 64.f);
        float var = q * (1.f / 64.f) - mu * mu;
        float rs = rsqrtf(var + 1e-5f);
        #pragma unroll
        for (int j = 0; j < 4; ++j) {
            int c = cg * 4 + j;
            es[(rg * 4 + i) * 68 + c] = (y[j] - mu) * rs * ln1g[c] + ln1b[c];
        }
    }
    __syncthreads();

    float h4[4][4];
    #pragma unroll
    for (int i = 0; i < 4; ++i)
        #pragma unroll
        for (int j = 0; j < 4; ++j) h4[i][j] = 0.f;
    for (int k = 0; k < 64; ++k) {
        float av[4];
        #pragma unroll
        for (int i = 0; i < 4; ++i) av[i] = es[(rg * 4 + i) * 68 + k];
        float4 bb = *(const float4*)(f1s + k * 68 + cg * 4);
        float bv[4] = {bb.x, bb.y, bb.z, bb.w};
        #pragma unroll
        for (int i = 0; i < 4; ++i)
            #pragma unroll
            for (int j = 0; j < 4; ++j) h4[i][j] += av[i] * bv[j];
    }
    #pragma unroll
    for (int i = 0; i < 4; ++i)
        #pragma unroll
        for (int j = 0; j < 4; ++j)
            hs[(rg * 4 + i) * 68 + cg * 4 + j] = fmaxf(h4[i][j], 0.f);
    __syncthreads();

    float fa[4][4];
    #pragma unroll
    for (int i = 0; i < 4; ++i)
        #pragma unroll
        for (int j = 0; j < 4; ++j) fa[i][j] = 0.f;
    for (int k = 0; k < 64; ++k) {
        float av[4];
        #pragma unroll
        for (int i = 0; i < 4; ++i) av[i] = hs[(rg * 4 + i) * 68 + k];
        float4 bb = *(const float4*)(f2s + k * 68 + cg * 4);
        float bv[4] = {bb.x, bb.y, bb.z, bb.w};
        #pragma unroll
        for (int i = 0; i < 4; ++i)
            #pragma unroll
            for (int j = 0; j < 4; ++j) fa[i][j] += av[i] * bv[j];
    }
    #pragma unroll
    for (int i = 0; i < 4; ++i) {
        float y[4];
        #pragma unroll
        for (int j = 0; j < 4; ++j) y[j] = fa[i][j] + es[(rg * 4 + i) * 68 + cg * 4 + j];
        float s = y[0] + y[1] + y[2] + y[3];
        float q = y[0]*y[0] + y[1]*y[1] + y[2]*y[2] + y[3]*y[3];
        #pragma unroll
        for (int o = 1; o < 16; o <<= 1) {
            s += __shfl_xor_sync(0xffffffffu, s, o);
            q += __shfl_xor_sync(0xffffffffu, q, o);
        }
        float mu = s * (1.f / 64.f);
        float var = q * (1.f / 64.f) - mu * mu;
        float rs = rsqrtf(var + 1e-5f);
        float4 o4;
        o4.x = (y[0] - mu) * rs * ln2g[cg * 4 + 0] + ln2b[cg * 4 + 0];
        o4.y = (y[1] - mu) * rs * ln2g[cg * 4 + 1] + ln2b[cg * 4 + 1];
        o4.z = (y[2] - mu) * rs * ln2g[cg * 4 + 2] + ln2b[cg * 4 + 2];
        o4.w = (y[3] - mu) * rs * ln2g[cg * 4 + 3] + ln2b[cg * 4 + 3];
        *(float4*)(res + (size_t)(row0 + rg * 4 + i) * 64 + cg * 4) = o4;
    }
}

// ---------------------------------------------------------------------------
// Launch
// ---------------------------------------------------------------------------
extern "C" void kernel_launch(void* const* d_in, const int* in_sizes, int n_in,
                              void* d_out, int out_size) {
    const float* x    = (const float*)d_in[0];
    const void*  mask = d_in[1];
    const float* u    = (const float*)d_in[2];
    const float* wq   = (const float*)d_in[3];
    const float* wk   = (const float*)d_in[4];
    const float* wv   = (const float*)d_in[5];
    const float* uqw  = (const float*)d_in[6];
    const float* ukw  = (const float*)d_in[7];
    const float* uvw  = (const float*)d_in[8];
    const float* sq1  = (const float*)d_in[9];
    const float* sq2  = (const float*)d_in[10];
    const float* sk1  = (const float*)d_in[11];
    const float* sk2  = (const float*)d_in[12];
    const float* sv1  = (const float*)d_in[13];
    const float* sv2  = (const float*)d_in[14];
    const float* fcw  = (const float*)d_in[15];
    const float* ln1g = (const float*)d_in[16];
    const float* ln1b = (const float*)d_in[17];
    const float* ffn1 = (const float*)d_in[18];
    const float* ffn2 = (const float*)d_in[19];
    const float* ln2g = (const float*)d_in[20];
    const float* ln2b = (const float*)d_in[21];

    float* res  = (float*)d_out;
    float* attn = res + (size_t)NB * SEQ * DM;

    cudaFuncSetAttribute(proj_kernel,  cudaFuncAttributeMaxDynamicSharedMemorySize, PROJ_SMEM_BYTES);
    cudaFuncSetAttribute(attn2_kernel, cudaFuncAttributeMaxDynamicSharedMemorySize, ATT_SMEM_BYTES);
    cudaFuncSetAttribute(post_kernel,  cudaFuncAttributeMaxDynamicSharedMemorySize, POST_SMEM_BYTES);

    detect_mask_kernel<<<1, 32>>>((const unsigned char*)mask);
    convert_mask_kernel<<<(NB * SEQ * SEQ) / 256, 256>>>(mask);
    gates_kernel<<<NB, 32>>>(u, sq1, sq2, sk1, sk2, sv1, sv2);
    proj_kernel<<<(NB * SEQ) / 32, 256, PROJ_SMEM_BYTES>>>(x, wq, wk, wv, uqw, ukw, uvw);
    attn2_kernel<<<NB * NH * (SEQ / TQ), 1024, ATT_SMEM_BYTES>>>(attn);
    norm_kernel<<<NB * NH * SEQ, 128>>>(attn);
    post_kernel<<<(NB * SEQ) / 64, 256, POST_SMEM_BYTES>>>(x, fcw, ln1g, ln1b, ffn1, ffn2,
                                                           ln2g, ln2b, res);
}

// round 7
// speedup vs baseline: 1.1947x; 1.1947x over previous
#include <cuda_runtime.h>
#include <cuda_fp16.h>
#include <cstdint>
#include <cstddef>

// ---------------------------------------------------------------------------
// Problem constants
// ---------------------------------------------------------------------------
#define NB   8
#define NH   4
#define SEQ  2048
#define DM   64

// attention tiling
#define TQ   32          // q rows per CTA
#define KSTR 132         // K tile row stride (floats)
#define VH   72          // half stride for vsh / psh rows

// ---------------------------------------------------------------------------
// Static device scratch
// ---------------------------------------------------------------------------
__device__ float    g_gates[3 * NB];
__device__ int      g_mask_mode;                           // 1 = int32 mask, 0 = byte mask
__device__ float    g_Qe[(size_t)NB * NH * SEQ * 128];     // 33.5 MB
__device__ float    g_Ke[(size_t)NB * NH * SEQ * 128];     // 33.5 MB
__device__ float    g_Ve[(size_t)NB * NH * SEQ * 64];      // 16.8 MB
__device__ __half   g_Veh[(size_t)NB * NH * 64 * SEQ];     // 8.4 MB (transposed [v][k] fp16)
__device__ float    g_ctx[(size_t)NB * SEQ * 256];         // 16.8 MB
__device__ unsigned g_maskb[(size_t)NB * SEQ * 64];        // 4 MB (bit-packed mask)

// ---------------------------------------------------------------------------
// Helpers
// ---------------------------------------------------------------------------
__device__ __forceinline__ float tf32r(float x) {
    float y;
    asm("cvt.rna.tf32.f32 %0, %1;" : "=f"(y) : "f"(x));
    return y;
}

__device__ __forceinline__ void mma_tf32(float& c0, float& c1, float& c2, float& c3,
                                         unsigned a0, unsigned a1, unsigned a2, unsigned a3,
                                         unsigned b0, unsigned b1) {
    asm volatile(
        "mma.sync.aligned.m16n8k8.row.col.f32.tf32.tf32.f32 "
        "{%0,%1,%2,%3},{%4,%5,%6,%7},{%8,%9},{%0,%1,%2,%3};"
        : "+f"(c0), "+f"(c1), "+f"(c2), "+f"(c3)
        : "r"(a0), "r"(a1), "r"(a2), "r"(a3), "r"(b0), "r"(b1));
}

__device__ __forceinline__ void mma_f16(float& c0, float& c1, float& c2, float& c3,
                                        unsigned a0, unsigned a1, unsigned b0) {
    asm volatile(
        "mma.sync.aligned.m16n8k8.row.col.f32.f16.f16.f32 "
        "{%0,%1,%2,%3},{%4,%5},{%6},{%0,%1,%2,%3};"
        : "+f"(c0), "+f"(c1), "+f"(c2), "+f"(c3)
        : "r"(a0), "r"(a1), "r"(b0));
}

__device__ __forceinline__ void cp_async16(void* smem, const void* gmem) {
    unsigned sa = (unsigned)__cvta_generic_to_shared(smem);
    asm volatile("cp.async.cg.shared.global [%0], [%1], 16;\n" :: "r"(sa), "l"(gmem));
}
__device__ __forceinline__ void cp_async8(void* smem, const void* gmem) {
    unsigned sa = (unsigned)__cvta_generic_to_shared(smem);
    asm volatile("cp.async.ca.shared.global [%0], [%1], 8;\n" :: "r"(sa), "l"(gmem));
}
__device__ __forceinline__ void cp_async4(void* smem, const void* gmem) {
    unsigned sa = (unsigned)__cvta_generic_to_shared(smem);
    asm volatile("cp.async.ca.shared.global [%0], [%1], 4;\n" :: "r"(sa), "l"(gmem));
}
#define CP_COMMIT() asm volatile("cp.async.commit_group;\n")
#define CP_WAIT(n)  asm volatile("cp.async.wait_group %0;\n" :: "n"(n))

// ---------------------------------------------------------------------------
// Kernel D: detect mask encoding (int32 vs byte)
// ---------------------------------------------------------------------------
__global__ void detect_mask_kernel(const unsigned char* __restrict__ m) {
    int found = 0;
    for (int i = threadIdx.x; i < 1024; i += 32)
        if (m[i * 4 + 1] | m[i * 4 + 2] | m[i * 4 + 3]) found = 1;
    for (int o = 16; o; o >>= 1)
        found |= __shfl_xor_sync(0xffffffffu, found, o);
    if (threadIdx.x == 0) g_mask_mode = found ? 0 : 1;
}

// ---------------------------------------------------------------------------
// Kernel M: bit-pack the mask (ballot-based, coalesced)
// ---------------------------------------------------------------------------
__global__ void __launch_bounds__(256) convert_mask_kernel(const void* __restrict__ mask) {
    unsigned gid = blockIdx.x * 256 + threadIdx.x;
    unsigned nz;
    if (g_mask_mode) nz = (((const int*)mask)[gid] != 0) ? 1u : 0u;
    else             nz = (((const unsigned char*)mask)[gid] != 0) ? 1u : 0u;
    unsigned bits = __ballot_sync(0xffffffffu, nz);
    if ((threadIdx.x & 31) == 0) g_maskb[gid >> 5] = bits;
}

// ---------------------------------------------------------------------------
// Kernel 0: scalar gates
// ---------------------------------------------------------------------------
__global__ void gates_kernel(const float* __restrict__ u,
                             const float* __restrict__ sq1, const float* __restrict__ sq2,
                             const float* __restrict__ sk1, const float* __restrict__ sk2,
                             const float* __restrict__ sv1, const float* __restrict__ sv2) {
    const int b = blockIdx.x;
    const int lane = threadIdx.x;
    float hq = 0.f, hk = 0.f, hv = 0.f;
    for (int d = 0; d < DM; ++d) {
        float uv = u[b * DM + d];
        hq += uv * sq1[d * 32 + lane];
        hk += uv * sk1[d * 32 + lane];
        hv += uv * sv1[d * 32 + lane];
    }
    hq = fmaxf(hq, 0.f) * sq2[lane];
    hk = fmaxf(hk, 0.f) * sk2[lane];
    hv = fmaxf(hv, 0.f) * sv2[lane];
    for (int off = 16; off; off >>= 1) {
        hq += __shfl_xor_sync(0xffffffffu, hq, off);
        hk += __shfl_xor_sync(0xffffffffu, hk, off);
        hv += __shfl_xor_sync(0xffffffffu, hv, off);
    }
    if (lane == 0) {
        g_gates[b]      = hq;
        g_gates[8 + b]  = hk;
        g_gates[16 + b] = hv;
    }
}

// ---------------------------------------------------------------------------
// Kernel 1: projections (R5 version — measured 124 us)
// ---------------------------------------------------------------------------
#define PROJ_SMEM_BYTES ((64*68 + 3*64*68 + 64*260) * 4)

__global__ void __launch_bounds__(256) proj_kernel(
    const float* __restrict__ x,
    const float* __restrict__ wq, const float* __restrict__ wk, const float* __restrict__ wv,
    const float* __restrict__ uqw, const float* __restrict__ ukw, const float* __restrict__ uvw) {
    extern __shared__ float sm[];
    float* xs   = sm;                 // 64 x 68
    float* uo   = xs + 64 * 68;       // 3 x (64 x 68)
    float* wbig = uo + 3 * 64 * 68;   // 64 x 260

    const int t = threadIdx.x;
    const int row0 = blockIdx.x * 64;
    const int b    = row0 >> 11;
    const int lr0  = row0 & (SEQ - 1);

    for (int i = t; i < 64 * 16; i += 256) {
        int r = i >> 4, c = (i & 15) * 4;
        *(float4*)(xs + r * 68 + c)              = *(const float4*)(x + (size_t)(row0 + r) * DM + c);
        *(float4*)(wbig + 0 * 4352 + r * 68 + c) = *(const float4*)(uqw + r * 64 + c);
        *(float4*)(wbig + 1 * 4352 + r * 68 + c) = *(const float4*)(ukw + r * 64 + c);
        *(float4*)(wbig + 2 * 4352 + r * 68 + c) = *(const float4*)(uvw + r * 64 + c);
    }
    __syncthreads();

    const int rg = t >> 5;
    const int cg = t & 31;

    if (cg < 24) {
        const int mat = cg >> 3;
        const int c0 = (cg & 7) * 8;
        const float* w = wbig + mat * 4352;
        float acc[8][8];
        #pragma unroll
        for (int i = 0; i < 8; ++i)
            #pragma unroll
            for (int j = 0; j < 8; ++j) acc[i][j] = 0.f;
        for (int k = 0; k < 64; ++k) {
            float av[8];
            #pragma unroll
            for (int i = 0; i < 8; ++i) av[i] = xs[(rg * 8 + i) * 68 + k];
            float4 b0 = *(const float4*)(w + k * 68 + c0);
            float4 b1 = *(const float4*)(w + k * 68 + c0 + 4);
            float bv[8] = {b0.x, b0.y, b0.z, b0.w, b1.x, b1.y, b1.z, b1.w};
            #pragma unroll
            for (int i = 0; i < 8; ++i)
                #pragma unroll
                for (int j = 0; j < 8; ++j) acc[i][j] += av[i] * bv[j];
        }
        float* dst = uo + mat * 4352;
        #pragma unroll
        for (int i = 0; i < 8; ++i)
            #pragma unroll
            for (int j = 0; j < 8; ++j)
                dst[(rg * 8 + i) * 68 + c0 + j] = acc[i][j];
    }
    __syncthreads();

    const float gq = g_gates[b] * 0.125f;
    const float gk = g_gates[8 + b];
    const float gv = g_gates[16 + b];

    for (int i = t; i < 64 * 64; i += 256) {
        int r = i >> 6, j = i & 63;
        float vq = tf32r(uo[r * 68 + j] * gq);
        float vk = tf32r(uo[4352 + r * 68 + j] * gk);
        size_t l = lr0 + r;
        #pragma unroll
        for (int h = 0; h < 4; ++h) {
            size_t base = (((size_t)b * 4 + h) * SEQ + l) * 128 + 64 + j;
            g_Qe[base] = vq;
            g_Ke[base] = vk;
        }
    }

    for (int m = 0; m < 3; ++m) {
        const float* w = (m == 0) ? wq : (m == 1) ? wk : wv;
        __syncthreads();
        for (int i = t; i < 64 * 64; i += 256) {
            int r = i >> 6, c = (i & 63) * 4;
            *(float4*)(wbig + r * 260 + c) = *(const float4*)(w + r * 256 + c);
        }
        __syncthreads();

        float acc[8][8];
        #pragma unroll
        for (int i = 0; i < 8; ++i)
            #pragma unroll
            for (int j = 0; j < 8; ++j) acc[i][j] = 0.f;
        for (int k = 0; k < 64; ++k) {
            float av[8];
            #pragma unroll
            for (int i = 0; i < 8; ++i) av[i] = xs[(rg * 8 + i) * 68 + k];
            float4 b0 = *(const float4*)(wbig + k * 260 + cg * 8);
            float4 b1 = *(const float4*)(wbig + k * 260 + cg * 8 + 4);
            float bv[8] = {b0.x, b0.y, b0.z, b0.w, b1.x, b1.y, b1.z, b1.w};
            #pragma unroll
            for (int i = 0; i < 8; ++i)
                #pragma unroll
                for (int j = 0; j < 8; ++j) acc[i][j] += av[i] * bv[j];
        }

        const int c0 = cg * 8;
        const int h  = c0 >> 6;
        const int j0 = c0 & 63;
        if (m == 2) {
            #pragma unroll
            for (int i = 0; i < 8; ++i) {
                size_t l = lr0 + rg * 8 + i;
                size_t base = (((size_t)b * 4 + h) * SEQ + l) * 64 + j0;
                #pragma unroll
                for (int j = 0; j < 8; ++j)
                    g_Ve[base + j] = acc[i][j] + uo[2 * 4352 + (rg * 8 + i) * 68 + j0 + j] * gv;
            }
        } else {
            float* tgt = (m == 0) ? g_Qe : g_Ke;
            float s = (m == 0) ? 0.125f : 1.0f;
            #pragma unroll
            for (int i = 0; i < 8; ++i) {
                size_t l = lr0 + rg * 8 + i;
                size_t base = (((size_t)b * 4 + h) * SEQ + l) * 128 + j0;
                #pragma unroll
                for (int j = 0; j < 8; ++j)
                    tgt[base + j] = tf32r(acc[i][j] * s);
            }
        }
    }
}

// ---------------------------------------------------------------------------
// Kernel 1b: transpose Ve -> g_Veh [bh][v][k] fp16
// ---------------------------------------------------------------------------
__global__ void __launch_bounds__(256) transpose_v_kernel() {
    __shared__ float ts[64][65];
    const int bh = blockIdx.x >> 5;
    const int kt = blockIdx.x & 31;
    const int t  = threadIdx.x;
    const float* src = g_Ve + ((size_t)bh * SEQ + kt * 64) * 64;
    for (int i = t; i < 64 * 16; i += 256) {
        int r = i >> 4, c = (i & 15) * 4;
        float4 v = *(const float4*)(src + (size_t)r * 64 + c);
        ts[r][c] = v.x; ts[r][c + 1] = v.y; ts[r][c + 2] = v.z; ts[r][c + 3] = v.w;
    }
    __syncthreads();
    __half* dst = g_Veh + (size_t)bh * 64 * SEQ + kt * 64;
    for (int i = t; i < 64 * 16; i += 256) {
        int v = i >> 4, k = (i & 15) * 4;
        __half2 h0 = __floats2half2_rn(ts[k][v],     ts[k + 1][v]);
        __half2 h1 = __floats2half2_rn(ts[k + 2][v], ts[k + 3][v]);
        *(__half2*)(dst + (size_t)v * SEQ + k)     = h0;
        *(__half2*)(dst + (size_t)v * SEQ + k + 2) = h1;
    }
}

// ---------------------------------------------------------------------------
// Kernel 2 (v4): attention. CTA = (b,h, 32 q-rows), 512 threads / 16 warps.
// QK tf32 mma (A hoisted), fp16 PV via C->A fragment reuse, V staged fp16
// transposed, p -> attn global direct from fragments (unnormalized), in-CTA
// global normalization pass at the end (replaces norm kernel).
// smem: qs 32x132 f | ks 2x64x132 f | vsh 2x64x72 h | psh 2x32x72 h |
//       red 256 f | inv 32 f | msb 2x64 u32      = 113,792 B
// ---------------------------------------------------------------------------
#define ATT_SMEM_BYTES ((TQ*KSTR + 2*64*KSTR + (2*64*VH)/2 + (2*TQ*VH)/2 + 256 + 32 + 128) * 4)

__global__ void __launch_bounds__(512) attn2_kernel(float* __restrict__ attn_out) {
    extern __shared__ float sm[];
    float*  qs  = sm;                              // 32 x 132
    float*  ks  = qs + TQ * KSTR;                  // 2 x 64 x 132
    __half* vsh = (__half*)(ks + 2 * 64 * KSTR);   // 2 x 64 x 72 halves
    __half* psh = vsh + 2 * 64 * VH;               // 2 x 32 x 72 halves
    float*  red = (float*)(psh + 2 * TQ * VH);     // 16 x 16
    float*  inv = red + 256;                       // 32
    unsigned* msb = (unsigned*)(inv + 32);         // 2 x 64

    const int t    = threadIdx.x;
    const int w    = t >> 5;
    const int lane = t & 31;
    const int g    = lane >> 2;
    const int tig  = lane & 3;
    const int qh   = w >> 3;               // 0/1: 16-row half
    const int n0   = (w & 7) * 8;          // k-col group within tile
    const int ra   = qh * 16 + g;
    const int rb   = ra + 8;

    const int bh = blockIdx.x >> 6;        // 64 q-tiles per (b,h)
    const int qt = blockIdx.x & 63;
    const int b  = bh >> 2;
    const int h  = bh & 3;
    const int q0 = qt * TQ;

    const float*  Qg = g_Qe + ((size_t)bh * SEQ + q0) * 128;
    const float*  Kg = g_Ke + (size_t)bh * SEQ * 128;
    const __half* Vg = g_Veh + (size_t)bh * 64 * SEQ;
    const unsigned* Mb = g_maskb + ((size_t)b * SEQ + q0) * 64;
    float* ao = attn_out + ((size_t)bh * SEQ + q0) * SEQ;

    // ---- stage Q + tile 0 ----
    for (int i = t; i < TQ * 32; i += 512) {
        int r = i >> 5, c = (i & 31) * 4;
        cp_async16(qs + r * KSTR + c, Qg + (size_t)r * 128 + c);
    }
    for (int i = t; i < 64 * 32; i += 512) {
        int r = i >> 5, c = (i & 31) * 4;
        cp_async16(ks + r * KSTR + c, Kg + (size_t)r * 128 + c);
    }
    for (int i = t; i < 64 * 16; i += 512) {
        int r = i >> 4, c8 = i & 15;
        cp_async8(vsh + r * VH + c8 * 4, Vg + (size_t)r * SEQ + c8 * 4);
    }
    if (t < 2 * TQ)
        cp_async4(msb + t, Mb + (size_t)(t >> 1) * 64 + (t & 1));
    CP_COMMIT();
    CP_WAIT(0);
    __syncthreads();

    // ---- hoist A (Q) fragments ----
    unsigned a[16][4];
    #pragma unroll
    for (int kk = 0; kk < 16; ++kk) {
        a[kk][0] = __float_as_uint(qs[ra * KSTR + kk * 8 + tig]);
        a[kk][1] = __float_as_uint(qs[rb * KSTR + kk * 8 + tig]);
        a[kk][2] = __float_as_uint(qs[ra * KSTR + kk * 8 + tig + 4]);
        a[kk][3] = __float_as_uint(qs[rb * KSTR + kk * 8 + tig + 4]);
    }

    float ctx0 = 0.f, ctx1 = 0.f, ctx2 = 0.f, ctx3 = 0.f;
    float sl0 = 0.f, sl1 = 0.f;
    const int col = n0 + 2 * tig;

    for (int tile = 0; tile < SEQ / 64; ++tile) {
        const int buf = tile & 1;
        const float*  kb = ks  + buf * 64 * KSTR;
        const __half* vb = vsh + buf * 64 * VH;
        const __half* pb = psh + buf * TQ * VH;
        const unsigned* mb = msb + buf * 2 * TQ;
        const int k0 = tile * 64;

        // ---- prefetch tile+1 (safe: all warps passed last tile's end sync) ----
        if (tile + 1 < SEQ / 64) {
            const int nb = buf ^ 1;
            const int nk0 = k0 + 64;
            for (int i = t; i < 64 * 32; i += 512) {
                int r = i >> 5, c = (i & 31) * 4;
                cp_async16(ks + nb * 64 * KSTR + r * KSTR + c,
                           Kg + (size_t)(nk0 + r) * 128 + c);
            }
            for (int i = t; i < 64 * 16; i += 512) {
                int r = i >> 4, c8 = i & 15;
                cp_async8(vsh + nb * 64 * VH + r * VH + c8 * 4,
                          Vg + (size_t)r * SEQ + nk0 + c8 * 4);
            }
            if (t < 2 * TQ)
                cp_async4(msb + nb * 2 * TQ + t,
                          Mb + (size_t)(t >> 1) * 64 + (nk0 >> 5) + (t & 1));
            CP_COMMIT();
        }

        // ---- QK scores ----
        float c0 = 0.f, c1 = 0.f, c2 = 0.f, c3 = 0.f;
        #pragma unroll
        for (int kk = 0; kk < 16; ++kk) {
            unsigned b0 = __float_as_uint(kb[(n0 + g) * KSTR + kk * 8 + tig]);
            unsigned b1 = __float_as_uint(kb[(n0 + g) * KSTR + kk * 8 + tig + 4]);
            mma_tf32(c0, c1, c2, c3, a[kk][0], a[kk][1], a[kk][2], a[kk][3], b0, b1);
        }

        // ---- mask + exp ----
        unsigned w0 = mb[ra * 2 + (col >> 5)];
        unsigned w1 = mb[rb * 2 + (col >> 5)];
        float p00 = ((w0 >> (col & 31)) & 1u)       ? 0.f : __expf(c0);
        float p01 = ((w0 >> ((col + 1) & 31)) & 1u) ? 0.f : __expf(c1);
        float p10 = ((w1 >> (col & 31)) & 1u)       ? 0.f : __expf(c2);
        float p11 = ((w1 >> ((col + 1) & 31)) & 1u) ? 0.f : __expf(c3);
        sl0 += p00 + p01;
        sl1 += p10 + p11;

        // ---- unnormalized p -> global (direct from fragments) ----
        *(float2*)(ao + (size_t)ra * SEQ + k0 + col) = make_float2(p00, p01);
        *(float2*)(ao + (size_t)rb * SEQ + k0 + col) = make_float2(p10, p11);

        // ---- p -> psh fp16 (A-fragment layout == C layout, no shuffle) ----
        *(__half2*)(psh + buf * TQ * VH + ra * VH + col) = __floats2half2_rn(p00, p01);
        *(__half2*)(psh + buf * TQ * VH + rb * VH + col) = __floats2half2_rn(p10, p11);
        __syncthreads();    // S1: psh complete

        // ---- fp16 PV: ctx[16][n0..n0+8] over the tile's 64 k ----
        #pragma unroll
        for (int kk = 0; kk < 8; ++kk) {
            unsigned pa0 = *(const unsigned*)(pb + ra * VH + kk * 8 + 2 * tig);
            unsigned pa1 = *(const unsigned*)(pb + rb * VH + kk * 8 + 2 * tig);
            unsigned vb0 = *(const unsigned*)(vb + (n0 + g) * VH + kk * 8 + 2 * tig);
            mma_f16(ctx0, ctx1, ctx2, ctx3, pa0, pa1, vb0);
        }

        CP_WAIT(0);
        __syncthreads();    // S2: next tile data in; buffers free
    }

    // ---- row-sum reduction ----
    sl0 += __shfl_xor_sync(0xffffffffu, sl0, 1);
    sl0 += __shfl_xor_sync(0xffffffffu, sl0, 2);
    sl1 += __shfl_xor_sync(0xffffffffu, sl1, 1);
    sl1 += __shfl_xor_sync(0xffffffffu, sl1, 2);
    if (tig == 0) {
        red[w * 16 + g]     = sl0;
        red[w * 16 + 8 + g] = sl1;
    }
    __syncthreads();
    if (t < TQ) {
        int qh_r = t >> 4;
        int rr   = t & 15;
        float s = 0.f;
        #pragma unroll
        for (int ww = 0; ww < 8; ++ww) s += red[(qh_r * 8 + ww) * 16 + rr];
        inv[t] = 1.f / s;
    }
    __syncthreads();

    // ---- normalized ctx write ----
    {
        float iv0 = inv[ra];
        float iv1 = inv[rb];
        size_t r0 = (size_t)b * SEQ + q0;
        *(float2*)(g_ctx + (r0 + ra) * 256 + h * 64 + col) = make_float2(ctx0 * iv0, ctx1 * iv0);
        *(float2*)(g_ctx + (r0 + rb) * 256 + h * 64 + col) = make_float2(ctx2 * iv1, ctx3 * iv1);
    }

    // ---- normalize this CTA's attn block in place (L2-resident) ----
    for (int i = t; i < TQ * 512; i += 512) {
        int r  = i >> 9;
        int c4 = i & 511;
        float iv = inv[r];
        float4* p = (float4*)(ao + (size_t)r * SEQ) + c4;
        float4 v = *p;
        v.x *= iv; v.y *= iv; v.z *= iv; v.w *= iv;
        *p = v;
    }
}

// ---------------------------------------------------------------------------
// Kernel 3: fc + LN1 + FFN + LN2 (unchanged)
// ---------------------------------------------------------------------------
#define POST_SMEM_BYTES ((64*260 + 256*68 + 4*64*68) * 4)

__global__ void __launch_bounds__(256) post_kernel(
    const float* __restrict__ x, const float* __restrict__ fcw,
    const float* __restrict__ ln1g, const float* __restrict__ ln1b,
    const float* __restrict__ f1, const float* __restrict__ f2,
    const float* __restrict__ ln2g, const float* __restrict__ ln2b,
    float* __restrict__ res) {
    extern __shared__ float sm[];
    float* cs  = sm;                 // 64 x 260
    float* fs  = cs + 64 * 260;      // 256 x 68
    float* hs  = fs + 256 * 68;      // 64 x 68
    float* es  = hs + 64 * 68;       // 64 x 68
    float* f1s = es + 64 * 68;       // 64 x 68
    float* f2s = f1s + 64 * 68;      // 64 x 68

    const int t = threadIdx.x;
    const int row0 = blockIdx.x * 64;

    for (int i = t; i < 64 * 64; i += 256) {
        int r = i >> 6, c = (i & 63) * 4;
        *(float4*)(cs + r * 260 + c) = *(const float4*)(g_ctx + (size_t)(row0 + r) * 256 + c);
    }
    for (int i = t; i < 256 * 16; i += 256) {
        int r = i >> 4, c = (i & 15) * 4;
        *(float4*)(fs + r * 68 + c) = *(const float4*)(fcw + r * 64 + c);
    }
    for (int i = t; i < 64 * 16; i += 256) {
        int r = i >> 4, c = (i & 15) * 4;
        *(float4*)(hs + r * 68 + c)  = *(const float4*)(x + (size_t)(row0 + r) * DM + c);
        *(float4*)(f1s + r * 68 + c) = *(const float4*)(f1 + r * 64 + c);
        *(float4*)(f2s + r * 68 + c) = *(const float4*)(f2 + r * 64 + c);
    }
    __syncthreads();

    const int rg = t >> 4;
    const int cg = t & 15;

    float acc[4][4];
    #pragma unroll
    for (int i = 0; i < 4; ++i)
        #pragma unroll
        for (int j = 0; j < 4; ++j) acc[i][j] = 0.f;
    for (int k = 0; k < 256; ++k) {
        float av[4];
        #pragma unroll
        for (int i = 0; i < 4; ++i) av[i] = cs[(rg * 4 + i) * 260 + k];
        float4 bb = *(const float4*)(fs + k * 68 + cg * 4);
        float bv[4] = {bb.x, bb.y, bb.z, bb.w};
        #pragma unroll
        for (int i = 0; i < 4; ++i)
            #pragma unroll
            for (int j = 0; j < 4; ++j) acc[i][j] += av[i] * bv[j];
    }

    #pragma unroll
    for (int i = 0; i < 4; ++i) {
        float y[4];
        #pragma unroll
        for (int j = 0; j < 4; ++j) y[j] = acc[i][j] + hs[(rg * 4 + i) * 68 + cg * 4 + j];
        float s = y[0] + y[1] + y[2] + y[3];
        float q = y[0]*y[0] + y[1]*y[1] + y[2]*y[2] + y[3]*y[3];
        #pragma unroll
        for (int o = 1; o < 16; o <<= 1) {
            s += __shfl_xor_sync(0xffffffffu, s, o);
            q += __shfl_xor_sync(0xffffffffu, q, o);
        }
        float mu = s * (1.f / 64.f);
        float var = q * (1.f / 64.f) - mu * mu;
        float rs = rsqrtf(var + 1e-5f);
        #pragma unroll
        for (int j = 0; j < 4; ++j) {
            int c = cg * 4 + j;
            es[(rg * 4 + i) * 68 + c] = (y[j] - mu) * rs * ln1g[c] + ln1b[c];
        }
    }
    __syncthreads();

    float h4[4][4];
    #pragma unroll
    for (int i = 0; i < 4; ++i)
        #pragma unroll
        for (int j = 0; j < 4; ++j) h4[i][j] = 0.f;
    for (int k = 0; k < 64; ++k) {
        float av[4];
        #pragma unroll
        for (int i = 0; i < 4; ++i) av[i] = es[(rg * 4 + i) * 68 + k];
        float4 bb = *(const float4*)(f1s + k * 68 + cg * 4);
        float bv[4] = {bb.x, bb.y, bb.z, bb.w};
        #pragma unroll
        for (int i = 0; i < 4; ++i)
            #pragma unroll
            for (int j = 0; j < 4; ++j) h4[i][j] += av[i] * bv[j];
    }
    #pragma unroll
    for (int i = 0; i < 4; ++i)
        #pragma unroll
        for (int j = 0; j < 4; ++j)
            hs[(rg * 4 + i) * 68 + cg * 4 + j] = fmaxf(h4[i][j], 0.f);
    __syncthreads();

    float fa[4][4];
    #pragma unroll
    for (int i = 0; i < 4; ++i)
        #pragma unroll
        for (int j = 0; j < 4; ++j) fa[i][j] = 0.f;
    for (int k = 0; k < 64; ++k) {
        float av[4];
        #pragma unroll
        for (int i = 0; i < 4; ++i) av[i] = hs[(rg * 4 + i) * 68 + k];
        float4 bb = *(const float4*)(f2s + k * 68 + cg * 4);
        float bv[4] = {bb.x, bb.y, bb.z, bb.w};
        #pragma unroll
        for (int i = 0; i < 4; ++i)
            #pragma unroll
            for (int j = 0; j < 4; ++j) fa[i][j] += av[i] * bv[j];
    }
    #pragma unroll
    for (int i = 0; i < 4; ++i) {
        float y[4];
        #pragma unroll
        for (int j = 0; j < 4; ++j) y[j] = fa[i][j] + es[(rg * 4 + i) * 68 + cg * 4 + j];
        float s = y[0] + y[1] + y[2] + y[3];
        float q = y[0]*y[0] + y[1]*y[1] + y[2]*y[2] + y[3]*y[3];
        #pragma unroll
        for (int o = 1; o < 16; o <<= 1) {
            s += __shfl_xor_sync(0xffffffffu, s, o);
            q += __shfl_xor_sync(0xffffffffu, q, o);
        }
        float mu = s * (1.f / 64.f);
        float var = q * (1.f / 64.f) - mu * mu;
        float rs = rsqrtf(var + 1e-5f);
        float4 o4;
        o4.x = (y[0] - mu) * rs * ln2g[cg * 4 + 0] + ln2b[cg * 4 + 0];
        o4.y = (y[1] - mu) * rs * ln2g[cg * 4 + 1] + ln2b[cg * 4 + 1];
        o4.z = (y[2] - mu) * rs * ln2g[cg * 4 + 2] + ln2b[cg * 4 + 2];
        o4.w = (y[3] - mu) * rs * ln2g[cg * 4 + 3] + ln2b[cg * 4 + 3];
        *(float4*)(res + (size_t)(row0 + rg * 4 + i) * 64 + cg * 4) = o4;
    }
}

// ---------------------------------------------------------------------------
// Launch
// ---------------------------------------------------------------------------
extern "C" void kernel_launch(void* const* d_in, const int* in_sizes, int n_in,
                              void* d_out, int out_size) {
    const float* x    = (const float*)d_in[0];
    const void*  mask = d_in[1];
    const float* u    = (const float*)d_in[2];
    const float* wq   = (const float*)d_in[3];
    const float* wk   = (const float*)d_in[4];
    const float* wv   = (const float*)d_in[5];
    const float* uqw  = (const float*)d_in[6];
    const float* ukw  = (const float*)d_in[7];
    const float* uvw  = (const float*)d_in[8];
    const float* sq1  = (const float*)d_in[9];
    const float* sq2  = (const float*)d_in[10];
    const float* sk1  = (const float*)d_in[11];
    const float* sk2  = (const float*)d_in[12];
    const float* sv1  = (const float*)d_in[13];
    const float* sv2  = (const float*)d_in[14];
    const float* fcw  = (const float*)d_in[15];
    const float* ln1g = (const float*)d_in[16];
    const float* ln1b = (const float*)d_in[17];
    const float* ffn1 = (const float*)d_in[18];
    const float* ffn2 = (const float*)d_in[19];
    const float* ln2g = (const float*)d_in[20];
    const float* ln2b = (const float*)d_in[21];

    float* res  = (float*)d_out;
    float* attn = res + (size_t)NB * SEQ * DM;

    cudaFuncSetAttribute(proj_kernel,  cudaFuncAttributeMaxDynamicSharedMemorySize, PROJ_SMEM_BYTES);
    cudaFuncSetAttribute(attn2_kernel, cudaFuncAttributeMaxDynamicSharedMemorySize, ATT_SMEM_BYTES);
    cudaFuncSetAttribute(post_kernel,  cudaFuncAttributeMaxDynamicSharedMemorySize, POST_SMEM_BYTES);

    detect_mask_kernel<<<1, 32>>>((const unsigned char*)mask);
    convert_mask_kernel<<<(NB * SEQ * SEQ) / 256, 256>>>(mask);
    gates_kernel<<<NB, 32>>>(u, sq1, sq2, sk1, sk2, sv1, sv2);
    proj_kernel<<<(NB * SEQ) / 64, 256, PROJ_SMEM_BYTES>>>(x, wq, wk, wv, uqw, ukw, uvw);
    transpose_v_kernel<<<NB * NH * 32, 256>>>();
    attn2_kernel<<<NB * NH * (SEQ / TQ), 512, ATT_SMEM_BYTES>>>(attn);
    post_kernel<<<(NB * SEQ) / 64, 256, POST_SMEM_BYTES>>>(x, fcw, ln1g, ln1b, ffn1, ffn2,
                                                           ln2g, ln2b, res);
}

// round 8
// speedup vs baseline: 1.6934x; 1.4174x over previous
#include <cuda_runtime.h>
#include <cuda_fp16.h>
#include <cstdint>
#include <cstddef>

// ---------------------------------------------------------------------------
// Problem constants
// ---------------------------------------------------------------------------
#define NB   8
#define NH   4
#define SEQ  2048
#define DM   64

// attention tiling
#define TQ   32          // q rows per CTA
#define KH   136         // half stride for qs/ks rows (128 data + 8 pad)
#define VH   72          // half stride for vsh / psh rows

// ---------------------------------------------------------------------------
// Static device scratch
// ---------------------------------------------------------------------------
__device__ float    g_gates[3 * NB];
__device__ int      g_mask_mode;                           // 1 = int32 mask, 0 = byte mask
__device__ __half   g_Qeh[(size_t)NB * NH * SEQ * 128];    // 16.8 MB fp16
__device__ __half   g_Keh[(size_t)NB * NH * SEQ * 128];    // 16.8 MB fp16
__device__ float    g_Ve[(size_t)NB * NH * SEQ * 64];      // 16.8 MB
__device__ __half   g_Veh[(size_t)NB * NH * 64 * SEQ];     // 8.4 MB (transposed [v][k] fp16)
__device__ float    g_ctx[(size_t)NB * SEQ * 256];         // 16.8 MB
__device__ unsigned g_maskb[(size_t)NB * SEQ * 64];        // 4 MB (bit-packed mask)

// ---------------------------------------------------------------------------
// Helpers
// ---------------------------------------------------------------------------
__device__ __forceinline__ void mma_f16_k16(float& c0, float& c1, float& c2, float& c3,
                                            unsigned a0, unsigned a1, unsigned a2, unsigned a3,
                                            unsigned b0, unsigned b1) {
    asm volatile(
        "mma.sync.aligned.m16n8k16.row.col.f32.f16.f16.f32 "
        "{%0,%1,%2,%3},{%4,%5,%6,%7},{%8,%9},{%0,%1,%2,%3};"
        : "+f"(c0), "+f"(c1), "+f"(c2), "+f"(c3)
        : "r"(a0), "r"(a1), "r"(a2), "r"(a3), "r"(b0), "r"(b1));
}

__device__ __forceinline__ void cp_async16(void* smem, const void* gmem) {
    unsigned sa = (unsigned)__cvta_generic_to_shared(smem);
    asm volatile("cp.async.cg.shared.global [%0], [%1], 16;\n" :: "r"(sa), "l"(gmem));
}
__device__ __forceinline__ void cp_async4(void* smem, const void* gmem) {
    unsigned sa = (unsigned)__cvta_generic_to_shared(smem);
    asm volatile("cp.async.ca.shared.global [%0], [%1], 4;\n" :: "r"(sa), "l"(gmem));
}
#define CP_COMMIT() asm volatile("cp.async.commit_group;\n")
#define CP_WAIT(n)  asm volatile("cp.async.wait_group %0;\n" :: "n"(n))

// ---------------------------------------------------------------------------
// Kernel D: detect mask encoding (int32 vs byte)
// ---------------------------------------------------------------------------
__global__ void detect_mask_kernel(const unsigned char* __restrict__ m) {
    int found = 0;
    for (int i = threadIdx.x; i < 1024; i += 32)
        if (m[i * 4 + 1] | m[i * 4 + 2] | m[i * 4 + 3]) found = 1;
    for (int o = 16; o; o >>= 1)
        found |= __shfl_xor_sync(0xffffffffu, found, o);
    if (threadIdx.x == 0) g_mask_mode = found ? 0 : 1;
}

// ---------------------------------------------------------------------------
// Kernel M: bit-pack the mask (ballot-based, coalesced)
// ---------------------------------------------------------------------------
__global__ void __launch_bounds__(256) convert_mask_kernel(const void* __restrict__ mask) {
    unsigned gid = blockIdx.x * 256 + threadIdx.x;
    unsigned nz;
    if (g_mask_mode) nz = (((const int*)mask)[gid] != 0) ? 1u : 0u;
    else             nz = (((const unsigned char*)mask)[gid] != 0) ? 1u : 0u;
    unsigned bits = __ballot_sync(0xffffffffu, nz);
    if ((threadIdx.x & 31) == 0) g_maskb[gid >> 5] = bits;
}

// ---------------------------------------------------------------------------
// Kernel 0: scalar gates
// ---------------------------------------------------------------------------
__global__ void gates_kernel(const float* __restrict__ u,
                             const float* __restrict__ sq1, const float* __restrict__ sq2,
                             const float* __restrict__ sk1, const float* __restrict__ sk2,
                             const float* __restrict__ sv1, const float* __restrict__ sv2) {
    const int b = blockIdx.x;
    const int lane = threadIdx.x;
    float hq = 0.f, hk = 0.f, hv = 0.f;
    for (int d = 0; d < DM; ++d) {
        float uv = u[b * DM + d];
        hq += uv * sq1[d * 32 + lane];
        hk += uv * sk1[d * 32 + lane];
        hv += uv * sv1[d * 32 + lane];
    }
    hq = fmaxf(hq, 0.f) * sq2[lane];
    hk = fmaxf(hk, 0.f) * sk2[lane];
    hv = fmaxf(hv, 0.f) * sv2[lane];
    for (int off = 16; off; off >>= 1) {
        hq += __shfl_xor_sync(0xffffffffu, hq, off);
        hk += __shfl_xor_sync(0xffffffffu, hk, off);
        hv += __shfl_xor_sync(0xffffffffu, hv, off);
    }
    if (lane == 0) {
        g_gates[b]      = hq;
        g_gates[8 + b]  = hk;
        g_gates[16 + b] = hv;
    }
}

// ---------------------------------------------------------------------------
// Kernel 1: projections -> fp16 Qe/Ke, fp32 Ve. (R5 structure, 124 us)
// ---------------------------------------------------------------------------
#define PROJ_SMEM_BYTES ((64*68 + 3*64*68 + 64*260) * 4)

__global__ void __launch_bounds__(256) proj_kernel(
    const float* __restrict__ x,
    const float* __restrict__ wq, const float* __restrict__ wk, const float* __restrict__ wv,
    const float* __restrict__ uqw, const float* __restrict__ ukw, const float* __restrict__ uvw) {
    extern __shared__ float sm[];
    float* xs   = sm;                 // 64 x 68
    float* uo   = xs + 64 * 68;       // 3 x (64 x 68)
    float* wbig = uo + 3 * 64 * 68;   // 64 x 260

    const int t = threadIdx.x;
    const int row0 = blockIdx.x * 64;
    const int b    = row0 >> 11;
    const int lr0  = row0 & (SEQ - 1);

    for (int i = t; i < 64 * 16; i += 256) {
        int r = i >> 4, c = (i & 15) * 4;
        *(float4*)(xs + r * 68 + c)              = *(const float4*)(x + (size_t)(row0 + r) * DM + c);
        *(float4*)(wbig + 0 * 4352 + r * 68 + c) = *(const float4*)(uqw + r * 64 + c);
        *(float4*)(wbig + 1 * 4352 + r * 68 + c) = *(const float4*)(ukw + r * 64 + c);
        *(float4*)(wbig + 2 * 4352 + r * 68 + c) = *(const float4*)(uvw + r * 64 + c);
    }
    __syncthreads();

    const int rg = t >> 5;
    const int cg = t & 31;

    if (cg < 24) {
        const int mat = cg >> 3;
        const int c0 = (cg & 7) * 8;
        const float* w = wbig + mat * 4352;
        float acc[8][8];
        #pragma unroll
        for (int i = 0; i < 8; ++i)
            #pragma unroll
            for (int j = 0; j < 8; ++j) acc[i][j] = 0.f;
        for (int k = 0; k < 64; ++k) {
            float av[8];
            #pragma unroll
            for (int i = 0; i < 8; ++i) av[i] = xs[(rg * 8 + i) * 68 + k];
            float4 b0 = *(const float4*)(w + k * 68 + c0);
            float4 b1 = *(const float4*)(w + k * 68 + c0 + 4);
            float bv[8] = {b0.x, b0.y, b0.z, b0.w, b1.x, b1.y, b1.z, b1.w};
            #pragma unroll
            for (int i = 0; i < 8; ++i)
                #pragma unroll
                for (int j = 0; j < 8; ++j) acc[i][j] += av[i] * bv[j];
        }
        float* dst = uo + mat * 4352;
        #pragma unroll
        for (int i = 0; i < 8; ++i)
            #pragma unroll
            for (int j = 0; j < 8; ++j)
                dst[(rg * 8 + i) * 68 + c0 + j] = acc[i][j];
    }
    __syncthreads();

    const float gq = g_gates[b] * 0.125f;
    const float gk = g_gates[8 + b];
    const float gv = g_gates[16 + b];

    // u-halves of Qe / Ke (fp16, same for all 4 heads)
    for (int i = t; i < 64 * 64; i += 256) {
        int r = i >> 6, j = i & 63;
        __half vq = __float2half(uo[r * 68 + j] * gq);
        __half vk = __float2half(uo[4352 + r * 68 + j] * gk);
        size_t l = lr0 + r;
        #pragma unroll
        for (int h = 0; h < 4; ++h) {
            size_t base = (((size_t)b * 4 + h) * SEQ + l) * 128 + 64 + j;
            g_Qeh[base] = vq;
            g_Keh[base] = vk;
        }
    }

    for (int m = 0; m < 3; ++m) {
        const float* w = (m == 0) ? wq : (m == 1) ? wk : wv;
        __syncthreads();
        for (int i = t; i < 64 * 64; i += 256) {
            int r = i >> 6, c = (i & 63) * 4;
            *(float4*)(wbig + r * 260 + c) = *(const float4*)(w + r * 256 + c);
        }
        __syncthreads();

        float acc[8][8];
        #pragma unroll
        for (int i = 0; i < 8; ++i)
            #pragma unroll
            for (int j = 0; j < 8; ++j) acc[i][j] = 0.f;
        for (int k = 0; k < 64; ++k) {
            float av[8];
            #pragma unroll
            for (int i = 0; i < 8; ++i) av[i] = xs[(rg * 8 + i) * 68 + k];
            float4 b0 = *(const float4*)(wbig + k * 260 + cg * 8);
            float4 b1 = *(const float4*)(wbig + k * 260 + cg * 8 + 4);
            float bv[8] = {b0.x, b0.y, b0.z, b0.w, b1.x, b1.y, b1.z, b1.w};
            #pragma unroll
            for (int i = 0; i < 8; ++i)
                #pragma unroll
                for (int j = 0; j < 8; ++j) acc[i][j] += av[i] * bv[j];
        }

        const int c0 = cg * 8;
        const int h  = c0 >> 6;
        const int j0 = c0 & 63;
        if (m == 2) {
            #pragma unroll
            for (int i = 0; i < 8; ++i) {
                size_t l = lr0 + rg * 8 + i;
                size_t base = (((size_t)b * 4 + h) * SEQ + l) * 64 + j0;
                #pragma unroll
                for (int j = 0; j < 8; ++j)
                    g_Ve[base + j] = acc[i][j] + uo[2 * 4352 + (rg * 8 + i) * 68 + j0 + j] * gv;
            }
        } else {
            __half* tgt = (m == 0) ? g_Qeh : g_Keh;
            float s = (m == 0) ? 0.125f : 1.0f;
            #pragma unroll
            for (int i = 0; i < 8; ++i) {
                size_t l = lr0 + rg * 8 + i;
                size_t base = (((size_t)b * 4 + h) * SEQ + l) * 128 + j0;
                #pragma unroll
                for (int j = 0; j < 8; j += 2)
                    *(__half2*)(tgt + base + j) =
                        __floats2half2_rn(acc[i][j] * s, acc[i][j + 1] * s);
            }
        }
    }
}

// ---------------------------------------------------------------------------
// Kernel 1b: transpose Ve -> g_Veh [bh][v][k] fp16
// ---------------------------------------------------------------------------
__global__ void __launch_bounds__(256) transpose_v_kernel() {
    __shared__ float ts[64][65];
    const int bh = blockIdx.x >> 5;
    const int kt = blockIdx.x & 31;
    const int t  = threadIdx.x;
    const float* src = g_Ve + ((size_t)bh * SEQ + kt * 64) * 64;
    for (int i = t; i < 64 * 16; i += 256) {
        int r = i >> 4, c = (i & 15) * 4;
        float4 v = *(const float4*)(src + (size_t)r * 64 + c);
        ts[r][c] = v.x; ts[r][c + 1] = v.y; ts[r][c + 2] = v.z; ts[r][c + 3] = v.w;
    }
    __syncthreads();
    __half* dst = g_Veh + (size_t)bh * 64 * SEQ + kt * 64;
    for (int i = t; i < 64 * 16; i += 256) {
        int v = i >> 4, k = (i & 15) * 4;
        __half2 h0 = __floats2half2_rn(ts[k][v],     ts[k + 1][v]);
        __half2 h1 = __floats2half2_rn(ts[k + 2][v], ts[k + 3][v]);
        *(__half2*)(dst + (size_t)v * SEQ + k)     = h0;
        *(__half2*)(dst + (size_t)v * SEQ + k + 2) = h1;
    }
}

// ---------------------------------------------------------------------------
// Kernel 2 (v5): attention, all-fp16 fragments (m16n8k16 QK + PV).
// CTA = (b,h, 32 q-rows), 512 threads / 16 warps, double-buffered cp.async.
// smem (halves): qs 32x136 | ks 2x64x136 | vsh 2x64x72 | psh 2x32x72
//       + red 256f | inv 32f | msb 2x64 u32   = 72,832 B
// ---------------------------------------------------------------------------
#define ATT_SMEM_BYTES ((TQ*KH + 2*64*KH + 2*64*VH + 2*TQ*VH) * 2 + 256*4 + 32*4 + 128*4)

__global__ void __launch_bounds__(512) attn2_kernel(float* __restrict__ attn_out) {
    extern __shared__ __half smh[];
    __half* qs  = smh;                       // 32 x 136
    __half* ks  = qs + TQ * KH;              // 2 x 64 x 136
    __half* vsh = ks + 2 * 64 * KH;          // 2 x 64 x 72
    __half* psh = vsh + 2 * 64 * VH;         // 2 x 32 x 72
    float*  red = (float*)(psh + 2 * TQ * VH);   // 16 x 16
    float*  inv = red + 256;                     // 32
    unsigned* msb = (unsigned*)(inv + 32);       // 2 x 64

    const int t    = threadIdx.x;
    const int w    = t >> 5;
    const int lane = t & 31;
    const int g    = lane >> 2;
    const int tig  = lane & 3;
    const int qh   = w >> 3;               // 0/1: 16-row half
    const int n0   = (w & 7) * 8;          // k-col group within tile
    const int ra   = qh * 16 + g;
    const int rb   = ra + 8;

    const int bh = blockIdx.x >> 6;        // 64 q-tiles per (b,h)
    const int qt = blockIdx.x & 63;
    const int b  = bh >> 2;
    const int h  = bh & 3;
    const int q0 = qt * TQ;

    const __half* Qg = g_Qeh + ((size_t)bh * SEQ + q0) * 128;
    const __half* Kg = g_Keh + (size_t)bh * SEQ * 128;
    const __half* Vg = g_Veh + (size_t)bh * 64 * SEQ;
    const unsigned* Mb = g_maskb + ((size_t)b * SEQ + q0) * 64;
    float* ao = attn_out + ((size_t)bh * SEQ + q0) * SEQ;

    // ---- stage Q + tile 0 (rows are 256 B of fp16 = 16 x 16B chunks) ----
    for (int i = t; i < TQ * 16; i += 512) {
        int r = i >> 4, c8 = (i & 15) * 8;
        cp_async16(qs + r * KH + c8, Qg + (size_t)r * 128 + c8);
    }
    for (int i = t; i < 64 * 16; i += 512) {
        int r = i >> 4, c8 = (i & 15) * 8;
        cp_async16(ks + r * KH + c8, Kg + (size_t)r * 128 + c8);
    }
    for (int i = t; i < 64 * 8; i += 512) {
        int r = i >> 3, c8 = (i & 7) * 8;
        cp_async16(vsh + r * VH + c8, Vg + (size_t)r * SEQ + c8);
    }
    if (t < 2 * TQ)
        cp_async4(msb + t, Mb + (size_t)(t >> 1) * 64 + (t & 1));
    CP_COMMIT();
    CP_WAIT(0);
    __syncthreads();

    // ---- hoist A (Q) fragments: 8 k16-chunks x 4 regs ----
    unsigned a[8][4];
    #pragma unroll
    for (int kk = 0; kk < 8; ++kk) {
        a[kk][0] = *(const unsigned*)(qs + ra * KH + kk * 16 + 2 * tig);
        a[kk][1] = *(const unsigned*)(qs + rb * KH + kk * 16 + 2 * tig);
        a[kk][2] = *(const unsigned*)(qs + ra * KH + kk * 16 + 2 * tig + 8);
        a[kk][3] = *(const unsigned*)(qs + rb * KH + kk * 16 + 2 * tig + 8);
    }

    float ctx0 = 0.f, ctx1 = 0.f, ctx2 = 0.f, ctx3 = 0.f;
    float sl0 = 0.f, sl1 = 0.f;
    const int col = n0 + 2 * tig;

    for (int tile = 0; tile < SEQ / 64; ++tile) {
        const int buf = tile & 1;
        const __half* kb = ks  + buf * 64 * KH;
        const __half* vb = vsh + buf * 64 * VH;
        const __half* pb = psh + buf * TQ * VH;
        const unsigned* mb = msb + buf * 2 * TQ;
        const int k0 = tile * 64;

        // ---- prefetch tile+1 ----
        if (tile + 1 < SEQ / 64) {
            const int nb = buf ^ 1;
            const int nk0 = k0 + 64;
            for (int i = t; i < 64 * 16; i += 512) {
                int r = i >> 4, c8 = (i & 15) * 8;
                cp_async16(ks + nb * 64 * KH + r * KH + c8,
                           Kg + (size_t)(nk0 + r) * 128 + c8);
            }
            for (int i = t; i < 64 * 8; i += 512) {
                int r = i >> 3, c8 = (i & 7) * 8;
                cp_async16(vsh + nb * 64 * VH + r * VH + c8,
                           Vg + (size_t)r * SEQ + nk0 + c8);
            }
            if (t < 2 * TQ)
                cp_async4(msb + nb * 2 * TQ + t,
                          Mb + (size_t)(t >> 1) * 64 + (nk0 >> 5) + (t & 1));
            CP_COMMIT();
        }

        // ---- QK scores: 8 fp16 k16 mmas ----
        float c0 = 0.f, c1 = 0.f, c2 = 0.f, c3 = 0.f;
        #pragma unroll
        for (int kk = 0; kk < 8; ++kk) {
            unsigned b0 = *(const unsigned*)(kb + (n0 + g) * KH + kk * 16 + 2 * tig);
            unsigned b1 = *(const unsigned*)(kb + (n0 + g) * KH + kk * 16 + 2 * tig + 8);
            mma_f16_k16(c0, c1, c2, c3, a[kk][0], a[kk][1], a[kk][2], a[kk][3], b0, b1);
        }

        // ---- mask + exp ----
        unsigned w0 = mb[ra * 2 + (col >> 5)];
        unsigned w1 = mb[rb * 2 + (col >> 5)];
        float p00 = ((w0 >> (col & 31)) & 1u)       ? 0.f : __expf(c0);
        float p01 = ((w0 >> ((col + 1) & 31)) & 1u) ? 0.f : __expf(c1);
        float p10 = ((w1 >> (col & 31)) & 1u)       ? 0.f : __expf(c2);
        float p11 = ((w1 >> ((col + 1) & 31)) & 1u) ? 0.f : __expf(c3);
        sl0 += p00 + p01;
        sl1 += p10 + p11;

        // ---- unnormalized p -> global (direct from fragments) ----
        *(float2*)(ao + (size_t)ra * SEQ + k0 + col) = make_float2(p00, p01);
        *(float2*)(ao + (size_t)rb * SEQ + k0 + col) = make_float2(p10, p11);

        // ---- p -> psh fp16 (C layout == A layout) ----
        *(__half2*)(psh + buf * TQ * VH + ra * VH + col) = __floats2half2_rn(p00, p01);
        *(__half2*)(psh + buf * TQ * VH + rb * VH + col) = __floats2half2_rn(p10, p11);
        __syncthreads();    // S1: psh complete

        // ---- fp16 PV: 4 k16 mmas ----
        #pragma unroll
        for (int kk = 0; kk < 4; ++kk) {
            unsigned pa0 = *(const unsigned*)(pb + ra * VH + kk * 16 + 2 * tig);
            unsigned pa1 = *(const unsigned*)(pb + rb * VH + kk * 16 + 2 * tig);
            unsigned pa2 = *(const unsigned*)(pb + ra * VH + kk * 16 + 2 * tig + 8);
            unsigned pa3 = *(const unsigned*)(pb + rb * VH + kk * 16 + 2 * tig + 8);
            unsigned vb0 = *(const unsigned*)(vb + (n0 + g) * VH + kk * 16 + 2 * tig);
            unsigned vb1 = *(const unsigned*)(vb + (n0 + g) * VH + kk * 16 + 2 * tig + 8);
            mma_f16_k16(ctx0, ctx1, ctx2, ctx3, pa0, pa1, pa2, pa3, vb0, vb1);
        }

        CP_WAIT(0);
        __syncthreads();    // S2: next tile visible; buffers free
    }

    // ---- row-sum reduction ----
    sl0 += __shfl_xor_sync(0xffffffffu, sl0, 1);
    sl0 += __shfl_xor_sync(0xffffffffu, sl0, 2);
    sl1 += __shfl_xor_sync(0xffffffffu, sl1, 1);
    sl1 += __shfl_xor_sync(0xffffffffu, sl1, 2);
    if (tig == 0) {
        red[w * 16 + g]     = sl0;
        red[w * 16 + 8 + g] = sl1;
    }
    __syncthreads();
    if (t < TQ) {
        int qh_r = t >> 4;
        int rr   = t & 15;
        float s = 0.f;
        #pragma unroll
        for (int ww = 0; ww < 8; ++ww) s += red[(qh_r * 8 + ww) * 16 + rr];
        inv[t] = 1.f / s;
    }
    __syncthreads();

    // ---- normalized ctx write ----
    {
        float iv0 = inv[ra];
        float iv1 = inv[rb];
        size_t r0 = (size_t)b * SEQ + q0;
        *(float2*)(g_ctx + (r0 + ra) * 256 + h * 64 + col) = make_float2(ctx0 * iv0, ctx1 * iv0);
        *(float2*)(g_ctx + (r0 + rb) * 256 + h * 64 + col) = make_float2(ctx2 * iv1, ctx3 * iv1);
    }

    // ---- normalize this CTA's attn block in place (L2-resident) ----
    for (int i = t; i < TQ * 512; i += 512) {
        int r  = i >> 9;
        int c4 = i & 511;
        float iv = inv[r];
        float4* p = (float4*)(ao + (size_t)r * SEQ) + c4;
        float4 v = *p;
        v.x *= iv; v.y *= iv; v.z *= iv; v.w *= iv;
        *p = v;
    }
}

// ---------------------------------------------------------------------------
// Kernel 3: fc + LN1 + FFN + LN2 (unchanged)
// ---------------------------------------------------------------------------
#define POST_SMEM_BYTES ((64*260 + 256*68 + 4*64*68) * 4)

__global__ void __launch_bounds__(256) post_kernel(
    const float* __restrict__ x, const float* __restrict__ fcw,
    const float* __restrict__ ln1g, const float* __restrict__ ln1b,
    const float* __restrict__ f1, const float* __restrict__ f2,
    const float* __restrict__ ln2g, const float* __restrict__ ln2b,
    float* __restrict__ res) {
    extern __shared__ float sm[];
    float* cs  = sm;                 // 64 x 260
    float* fs  = cs + 64 * 260;      // 256 x 68
    float* hs  = fs + 256 * 68;      // 64 x 68
    float* es  = hs + 64 * 68;       // 64 x 68
    float* f1s = es + 64 * 68;       // 64 x 68
    float* f2s = f1s + 64 * 68;      // 64 x 68

    const int t = threadIdx.x;
    const int row0 = blockIdx.x * 64;

    for (int i = t; i < 64 * 64; i += 256) {
        int r = i >> 6, c = (i & 63) * 4;
        *(float4*)(cs + r * 260 + c) = *(const float4*)(g_ctx + (size_t)(row0 + r) * 256 + c);
    }
    for (int i = t; i < 256 * 16; i += 256) {
        int r = i >> 4, c = (i & 15) * 4;
        *(float4*)(fs + r * 68 + c) = *(const float4*)(fcw + r * 64 + c);
    }
    for (int i = t; i < 64 * 16; i += 256) {
        int r = i >> 4, c = (i & 15) * 4;
        *(float4*)(hs + r * 68 + c)  = *(const float4*)(x + (size_t)(row0 + r) * DM + c);
        *(float4*)(f1s + r * 68 + c) = *(const float4*)(f1 + r * 64 + c);
        *(float4*)(f2s + r * 68 + c) = *(const float4*)(f2 + r * 64 + c);
    }
    __syncthreads();

    const int rg = t >> 4;
    const int cg = t & 15;

    float acc[4][4];
    #pragma unroll
    for (int i = 0; i < 4; ++i)
        #pragma unroll
        for (int j = 0; j < 4; ++j) acc[i][j] = 0.f;
    for (int k = 0; k < 256; ++k) {
        float av[4];
        #pragma unroll
        for (int i = 0; i < 4; ++i) av[i] = cs[(rg * 4 + i) * 260 + k];
        float4 bb = *(const float4*)(fs + k * 68 + cg * 4);
        float bv[4] = {bb.x, bb.y, bb.z, bb.w};
        #pragma unroll
        for (int i = 0; i < 4; ++i)
            #pragma unroll
            for (int j = 0; j < 4; ++j) acc[i][j] += av[i] * bv[j];
    }

    #pragma unroll
    for (int i = 0; i < 4; ++i) {
        float y[4];
        #pragma unroll
        for (int j = 0; j < 4; ++j) y[j] = acc[i][j] + hs[(rg * 4 + i) * 68 + cg * 4 + j];
        float s = y[0] + y[1] + y[2] + y[3];
        float q = y[0]*y[0] + y[1]*y[1] + y[2]*y[2] + y[3]*y[3];
        #pragma unroll
        for (int o = 1; o < 16; o <<= 1) {
            s += __shfl_xor_sync(0xffffffffu, s, o);
            q += __shfl_xor_sync(0xffffffffu, q, o);
        }
        float mu = s * (1.f / 64.f);
        float var = q * (1.f / 64.f) - mu * mu;
        float rs = rsqrtf(var + 1e-5f);
        #pragma unroll
        for (int j = 0; j < 4; ++j) {
            int c = cg * 4 + j;
            es[(rg * 4 + i) * 68 + c] = (y[j] - mu) * rs * ln1g[c] + ln1b[c];
        }
    }
    __syncthreads();

    float h4[4][4];
    #pragma unroll
    for (int i = 0; i < 4; ++i)
        #pragma unroll
        for (int j = 0; j < 4; ++j) h4[i][j] = 0.f;
    for (int k = 0; k < 64; ++k) {
        float av[4];
        #pragma unroll
        for (int i = 0; i < 4; ++i) av[i] = es[(rg * 4 + i) * 68 + k];
        float4 bb = *(const float4*)(f1s + k * 68 + cg * 4);
        float bv[4] = {bb.x, bb.y, bb.z, bb.w};
        #pragma unroll
        for (int i = 0; i < 4; ++i)
            #pragma unroll
            for (int j = 0; j < 4; ++j) h4[i][j] += av[i] * bv[j];
    }
    #pragma unroll
    for (int i = 0; i < 4; ++i)
        #pragma unroll
        for (int j = 0; j < 4; ++j)
            hs[(rg * 4 + i) * 68 + cg * 4 + j] = fmaxf(h4[i][j], 0.f);
    __syncthreads();

    float fa[4][4];
    #pragma unroll
    for (int i = 0; i < 4; ++i)
        #pragma unroll
        for (int j = 0; j < 4; ++j) fa[i][j] = 0.f;
    for (int k = 0; k < 64; ++k) {
        float av[4];
        #pragma unroll
        for (int i = 0; i < 4; ++i) av[i] = hs[(rg * 4 + i) * 68 + k];
        float4 bb = *(const float4*)(f2s + k * 68 + cg * 4);
        float bv[4] = {bb.x, bb.y, bb.z, bb.w};
        #pragma unroll
        for (int i = 0; i < 4; ++i)
            #pragma unroll
            for (int j = 0; j < 4; ++j) fa[i][j] += av[i] * bv[j];
    }
    #pragma unroll
    for (int i = 0; i < 4; ++i) {
        float y[4];
        #pragma unroll
        for (int j = 0; j < 4; ++j) y[j] = fa[i][j] + es[(rg * 4 + i) * 68 + cg * 4 + j];
        float s = y[0] + y[1] + y[2] + y[3];
        float q = y[0]*y[0] + y[1]*y[1] + y[2]*y[2] + y[3]*y[3];
        #pragma unroll
        for (int o = 1; o < 16; o <<= 1) {
            s += __shfl_xor_sync(0xffffffffu, s, o);
            q += __shfl_xor_sync(0xffffffffu, q, o);
        }
        float mu = s * (1.f / 64.f);
        float var = q * (1.f / 64.f) - mu * mu;
        float rs = rsqrtf(var + 1e-5f);
        float4 o4;
        o4.x = (y[0] - mu) * rs * ln2g[cg * 4 + 0] + ln2b[cg * 4 + 0];
        o4.y = (y[1] - mu) * rs * ln2g[cg * 4 + 1] + ln2b[cg * 4 + 1];
        o4.z = (y[2] - mu) * rs * ln2g[cg * 4 + 2] + ln2b[cg * 4 + 2];
        o4.w = (y[3] - mu) * rs * ln2g[cg * 4 + 3] + ln2b[cg * 4 + 3];
        *(float4*)(res + (size_t)(row0 + rg * 4 + i) * 64 + cg * 4) = o4;
    }
}

// ---------------------------------------------------------------------------
// Launch
// ---------------------------------------------------------------------------
extern "C" void kernel_launch(void* const* d_in, const int* in_sizes, int n_in,
                              void* d_out, int out_size) {
    const float* x    = (const float*)d_in[0];
    const void*  mask = d_in[1];
    const float* u    = (const float*)d_in[2];
    const float* wq   = (const float*)d_in[3];
    const float* wk   = (const float*)d_in[4];
    const float* wv   = (const float*)d_in[5];
    const float* uqw  = (const float*)d_in[6];
    const float* ukw  = (const float*)d_in[7];
    const float* uvw  = (const float*)d_in[8];
    const float* sq1  = (const float*)d_in[9];
    const float* sq2  = (const float*)d_in[10];
    const float* sk1  = (const float*)d_in[11];
    const float* sk2  = (const float*)d_in[12];
    const float* sv1  = (const float*)d_in[13];
    const float* sv2  = (const float*)d_in[14];
    const float* fcw  = (const float*)d_in[15];
    const float* ln1g = (const float*)d_in[16];
    const float* ln1b = (const float*)d_in[17];
    const float* ffn1 = (const float*)d_in[18];
    const float* ffn2 = (const float*)d_in[19];
    const float* ln2g = (const float*)d_in[20];
    const float* ln2b = (const float*)d_in[21];

    float* res  = (float*)d_out;
    float* attn = res + (size_t)NB * SEQ * DM;

    cudaFuncSetAttribute(proj_kernel,  cudaFuncAttributeMaxDynamicSharedMemorySize, PROJ_SMEM_BYTES);
    cudaFuncSetAttribute(attn2_kernel, cudaFuncAttributeMaxDynamicSharedMemorySize, ATT_SMEM_BYTES);
    cudaFuncSetAttribute(post_kernel,  cudaFuncAttributeMaxDynamicSharedMemorySize, POST_SMEM_BYTES);

    detect_mask_kernel<<<1, 32>>>((const unsigned char*)mask);
    convert_mask_kernel<<<(NB * SEQ * SEQ) / 256, 256>>>(mask);
    gates_kernel<<<NB, 32>>>(u, sq1, sq2, sk1, sk2, sv1, sv2);
    proj_kernel<<<(NB * SEQ) / 64, 256, PROJ_SMEM_BYTES>>>(x, wq, wk, wv, uqw, ukw, uvw);
    transpose_v_kernel<<<NB * NH * 32, 256>>>();
    attn2_kernel<<<NB * NH * (SEQ / TQ), 512, ATT_SMEM_BYTES>>>(attn);
    post_kernel<<<(NB * SEQ) / 64, 256, POST_SMEM_BYTES>>>(x, fcw, ln1g, ln1b, ffn1, ffn2,
                                                           ln2g, ln2b, res);
}

// round 9
// speedup vs baseline: 1.7615x; 1.0402x over previous
#include <cuda_runtime.h>
#include <cuda_fp16.h>
#include <cstdint>
#include <cstddef>

// ---------------------------------------------------------------------------
// Problem constants
// ---------------------------------------------------------------------------
#define NB   8
#define NH   4
#define SEQ  2048
#define DM   64

// attention tiling
#define TQ   32          // q rows per CTA
#define KH   136         // half stride for qs/ks rows (128 data + 8 pad)
#define VH   72          // half stride for vsh / psh rows

// ---------------------------------------------------------------------------
// Static device scratch
// ---------------------------------------------------------------------------
__device__ float    g_gates[3 * NB];
__device__ int      g_mask_mode;                           // 1 = int32 mask, 0 = byte mask
__device__ __half   g_Qeh[(size_t)NB * NH * SEQ * 128];    // 16.8 MB fp16
__device__ __half   g_Keh[(size_t)NB * NH * SEQ * 128];    // 16.8 MB fp16
__device__ float    g_Ve[(size_t)NB * NH * SEQ * 64];      // 16.8 MB
__device__ __half   g_Veh[(size_t)NB * NH * 64 * SEQ];     // 8.4 MB (transposed [v][k] fp16)
__device__ float    g_ctx[(size_t)NB * SEQ * 256];         // 16.8 MB
__device__ unsigned g_maskb[(size_t)NB * SEQ * 64];        // 4 MB (bit-packed mask)
__device__ __half   g_ph[(size_t)NB * NH * SEQ * SEQ];     // 268 MB fp16 p scratch

// ---------------------------------------------------------------------------
// Helpers
// ---------------------------------------------------------------------------
__device__ __forceinline__ void mma_f16_k16(float& c0, float& c1, float& c2, float& c3,
                                            unsigned a0, unsigned a1, unsigned a2, unsigned a3,
                                            unsigned b0, unsigned b1) {
    asm volatile(
        "mma.sync.aligned.m16n8k16.row.col.f32.f16.f16.f32 "
        "{%0,%1,%2,%3},{%4,%5,%6,%7},{%8,%9},{%0,%1,%2,%3};"
        : "+f"(c0), "+f"(c1), "+f"(c2), "+f"(c3)
        : "r"(a0), "r"(a1), "r"(a2), "r"(a3), "r"(b0), "r"(b1));
}

__device__ __forceinline__ void cp_async16(void* smem, const void* gmem) {
    unsigned sa = (unsigned)__cvta_generic_to_shared(smem);
    asm volatile("cp.async.cg.shared.global [%0], [%1], 16;\n" :: "r"(sa), "l"(gmem));
}
__device__ __forceinline__ void cp_async4(void* smem, const void* gmem) {
    unsigned sa = (unsigned)__cvta_generic_to_shared(smem);
    asm volatile("cp.async.ca.shared.global [%0], [%1], 4;\n" :: "r"(sa), "l"(gmem));
}
#define CP_COMMIT() asm volatile("cp.async.commit_group;\n")
#define CP_WAIT(n)  asm volatile("cp.async.wait_group %0;\n" :: "n"(n))

// ---------------------------------------------------------------------------
// Kernel D: detect mask encoding (int32 vs byte)
// ---------------------------------------------------------------------------
__global__ void detect_mask_kernel(const unsigned char* __restrict__ m) {
    int found = 0;
    for (int i = threadIdx.x; i < 1024; i += 32)
        if (m[i * 4 + 1] | m[i * 4 + 2] | m[i * 4 + 3]) found = 1;
    for (int o = 16; o; o >>= 1)
        found |= __shfl_xor_sync(0xffffffffu, found, o);
    if (threadIdx.x == 0) g_mask_mode = found ? 0 : 1;
}

// ---------------------------------------------------------------------------
// Kernel M: bit-pack the mask (ballot-based, coalesced)
// ---------------------------------------------------------------------------
__global__ void __launch_bounds__(256) convert_mask_kernel(const void* __restrict__ mask) {
    unsigned gid = blockIdx.x * 256 + threadIdx.x;
    unsigned nz;
    if (g_mask_mode) nz = (((const int*)mask)[gid] != 0) ? 1u : 0u;
    else             nz = (((const unsigned char*)mask)[gid] != 0) ? 1u : 0u;
    unsigned bits = __ballot_sync(0xffffffffu, nz);
    if ((threadIdx.x & 31) == 0) g_maskb[gid >> 5] = bits;
}

// ---------------------------------------------------------------------------
// Kernel 0: scalar gates
// ---------------------------------------------------------------------------
__global__ void gates_kernel(const float* __restrict__ u,
                             const float* __restrict__ sq1, const float* __restrict__ sq2,
                             const float* __restrict__ sk1, const float* __restrict__ sk2,
                             const float* __restrict__ sv1, const float* __restrict__ sv2) {
    const int b = blockIdx.x;
    const int lane = threadIdx.x;
    float hq = 0.f, hk = 0.f, hv = 0.f;
    for (int d = 0; d < DM; ++d) {
        float uv = u[b * DM + d];
        hq += uv * sq1[d * 32 + lane];
        hk += uv * sk1[d * 32 + lane];
        hv += uv * sv1[d * 32 + lane];
    }
    hq = fmaxf(hq, 0.f) * sq2[lane];
    hk = fmaxf(hk, 0.f) * sk2[lane];
    hv = fmaxf(hv, 0.f) * sv2[lane];
    for (int off = 16; off; off >>= 1) {
        hq += __shfl_xor_sync(0xffffffffu, hq, off);
        hk += __shfl_xor_sync(0xffffffffu, hk, off);
        hv += __shfl_xor_sync(0xffffffffu, hv, off);
    }
    if (lane == 0) {
        g_gates[b]      = hq;
        g_gates[8 + b]  = hk;
        g_gates[16 + b] = hv;
    }
}

// ---------------------------------------------------------------------------
// Kernel 1 (v3): projections, 2 CTAs/SM. Weight tiles in 64x132 halves.
// smem: xs 64x68 | uo 3x(64x68) (weights then outputs) | wbig 64x132 = 103 KB
// ---------------------------------------------------------------------------
#define PROJ_SMEM_BYTES ((64*68 + 3*64*68 + 64*132) * 4)

__global__ void __launch_bounds__(256, 2) proj_kernel(
    const float* __restrict__ x,
    const float* __restrict__ wq, const float* __restrict__ wk, const float* __restrict__ wv,
    const float* __restrict__ uqw, const float* __restrict__ ukw, const float* __restrict__ uvw) {
    extern __shared__ float sm[];
    float* xs   = sm;                 // 64 x 68
    float* uo   = xs + 64 * 68;       // 3 x (64 x 68): u-weights, then u outputs
    float* wbig = uo + 3 * 64 * 68;   // 64 x 132

    const int t = threadIdx.x;
    const int row0 = blockIdx.x * 64;
    const int b    = row0 >> 11;
    const int lr0  = row0 & (SEQ - 1);

    // stage x tile and the three u-weight matrices (into uo region)
    for (int i = t; i < 64 * 16; i += 256) {
        int r = i >> 4, c = (i & 15) * 4;
        *(float4*)(xs + r * 68 + c)            = *(const float4*)(x + (size_t)(row0 + r) * DM + c);
        *(float4*)(uo + 0 * 4352 + r * 68 + c) = *(const float4*)(uqw + r * 64 + c);
        *(float4*)(uo + 1 * 4352 + r * 68 + c) = *(const float4*)(ukw + r * 64 + c);
        *(float4*)(uo + 2 * 4352 + r * 68 + c) = *(const float4*)(uvw + r * 64 + c);
    }
    __syncthreads();

    const int rg = t >> 5;     // 8 groups x 8 rows
    const int cg = t & 31;

    // u projections: accumulate into registers (weights read from uo region)
    float uacc[8][8];
    if (cg < 24) {
        const int mat = cg >> 3;
        const int c0 = (cg & 7) * 8;
        const float* w = uo + mat * 4352;
        #pragma unroll
        for (int i = 0; i < 8; ++i)
            #pragma unroll
            for (int j = 0; j < 8; ++j) uacc[i][j] = 0.f;
        for (int k = 0; k < 64; ++k) {
            float av[8];
            #pragma unroll
            for (int i = 0; i < 8; ++i) av[i] = xs[(rg * 8 + i) * 68 + k];
            float4 b0 = *(const float4*)(w + k * 68 + c0);
            float4 b1 = *(const float4*)(w + k * 68 + c0 + 4);
            float bv[8] = {b0.x, b0.y, b0.z, b0.w, b1.x, b1.y, b1.z, b1.w};
            #pragma unroll
            for (int i = 0; i < 8; ++i)
                #pragma unroll
                for (int j = 0; j < 8; ++j) uacc[i][j] += av[i] * bv[j];
        }
    }
    __syncthreads();   // all weight reads complete before overwrite

    if (cg < 24) {
        const int mat = cg >> 3;
        const int c0 = (cg & 7) * 8;
        float* dst = uo + mat * 4352;
        #pragma unroll
        for (int i = 0; i < 8; ++i)
            #pragma unroll
            for (int j = 0; j < 8; ++j)
                dst[(rg * 8 + i) * 68 + c0 + j] = uacc[i][j];
    }
    __syncthreads();

    const float gq = g_gates[b] * 0.125f;
    const float gk = g_gates[8 + b];
    const float gv = g_gates[16 + b];

    // u-halves of Qe / Ke (fp16, same for all 4 heads)
    for (int i = t; i < 64 * 64; i += 256) {
        int r = i >> 6, j = i & 63;
        __half vq = __float2half(uo[r * 68 + j] * gq);
        __half vk = __float2half(uo[4352 + r * 68 + j] * gk);
        size_t l = lr0 + r;
        #pragma unroll
        for (int h = 0; h < 4; ++h) {
            size_t base = (((size_t)b * 4 + h) * SEQ + l) * 128 + 64 + j;
            g_Qeh[base] = vq;
            g_Keh[base] = vk;
        }
    }

    // big GEMMs: Q, K, V — each weight in two 128-column halves
    for (int m = 0; m < 3; ++m) {
        const float* w = (m == 0) ? wq : (m == 1) ? wk : wv;
        for (int h2 = 0; h2 < 2; ++h2) {
            __syncthreads();
            for (int i = t; i < 64 * 32; i += 256) {
                int r = i >> 5, c = (i & 31) * 4;
                *(float4*)(wbig + r * 132 + c) = *(const float4*)(w + r * 256 + h2 * 128 + c);
            }
            __syncthreads();

            float acc[8][4];
            #pragma unroll
            for (int i = 0; i < 8; ++i)
                #pragma unroll
                for (int j = 0; j < 4; ++j) acc[i][j] = 0.f;
            for (int k = 0; k < 64; ++k) {
                float av[8];
                #pragma unroll
                for (int i = 0; i < 8; ++i) av[i] = xs[(rg * 8 + i) * 68 + k];
                float4 bb = *(const float4*)(wbig + k * 132 + cg * 4);
                float bv[4] = {bb.x, bb.y, bb.z, bb.w};
                #pragma unroll
                for (int i = 0; i < 8; ++i)
                    #pragma unroll
                    for (int j = 0; j < 4; ++j) acc[i][j] += av[i] * bv[j];
            }

            const int gc = h2 * 128 + cg * 4;
            const int h  = gc >> 6;
            const int j0 = gc & 63;
            if (m == 2) {
                #pragma unroll
                for (int i = 0; i < 8; ++i) {
                    size_t l = lr0 + rg * 8 + i;
                    size_t base = (((size_t)b * 4 + h) * SEQ + l) * 64 + j0;
                    #pragma unroll
                    for (int j = 0; j < 4; ++j)
                        g_Ve[base + j] = acc[i][j] + uo[2 * 4352 + (rg * 8 + i) * 68 + j0 + j] * gv;
                }
            } else {
                __half* tgt = (m == 0) ? g_Qeh : g_Keh;
                float s = (m == 0) ? 0.125f : 1.0f;
                #pragma unroll
                for (int i = 0; i < 8; ++i) {
                    size_t l = lr0 + rg * 8 + i;
                    size_t base = (((size_t)b * 4 + h) * SEQ + l) * 128 + j0;
                    *(__half2*)(tgt + base)     = __floats2half2_rn(acc[i][0] * s, acc[i][1] * s);
                    *(__half2*)(tgt + base + 2) = __floats2half2_rn(acc[i][2] * s, acc[i][3] * s);
                }
            }
        }
    }
}

// ---------------------------------------------------------------------------
// Kernel 1b: transpose Ve -> g_Veh [bh][v][k] fp16
// ---------------------------------------------------------------------------
__global__ void __launch_bounds__(256) transpose_v_kernel() {
    __shared__ float ts[64][65];
    const int bh = blockIdx.x >> 5;
    const int kt = blockIdx.x & 31;
    const int t  = threadIdx.x;
    const float* src = g_Ve + ((size_t)bh * SEQ + kt * 64) * 64;
    for (int i = t; i < 64 * 16; i += 256) {
        int r = i >> 4, c = (i & 15) * 4;
        float4 v = *(const float4*)(src + (size_t)r * 64 + c);
        ts[r][c] = v.x; ts[r][c + 1] = v.y; ts[r][c + 2] = v.z; ts[r][c + 3] = v.w;
    }
    __syncthreads();
    __half* dst = g_Veh + (size_t)bh * 64 * SEQ + kt * 64;
    for (int i = t; i < 64 * 16; i += 256) {
        int v = i >> 4, k = (i & 15) * 4;
        __half2 h0 = __floats2half2_rn(ts[k][v],     ts[k + 1][v]);
        __half2 h1 = __floats2half2_rn(ts[k + 2][v], ts[k + 3][v]);
        *(__half2*)(dst + (size_t)v * SEQ + k)     = h0;
        *(__half2*)(dst + (size_t)v * SEQ + k + 2) = h1;
    }
}

// ---------------------------------------------------------------------------
// Kernel 2 (v6): attention, fp16 fragments + fp16 p scratch.
// In-loop p stores go to g_ph (fp16, half the bytes); the fp32 attn output is
// written exactly once by the in-CTA normalize tail (reads own L2-warm block).
// ---------------------------------------------------------------------------
#define ATT_SMEM_BYTES ((TQ*KH + 2*64*KH + 2*64*VH + 2*TQ*VH) * 2 + 256*4 + 32*4 + 128*4)

__global__ void __launch_bounds__(512) attn2_kernel(float* __restrict__ attn_out) {
    extern __shared__ __half smh[];
    __half* qs  = smh;                       // 32 x 136
    __half* ks  = qs + TQ * KH;              // 2 x 64 x 136
    __half* vsh = ks + 2 * 64 * KH;          // 2 x 64 x 72
    __half* psh = vsh + 2 * 64 * VH;         // 2 x 32 x 72
    float*  red = (float*)(psh + 2 * TQ * VH);   // 16 x 16
    float*  inv = red + 256;                     // 32
    unsigned* msb = (unsigned*)(inv + 32);       // 2 x 64

    const int t    = threadIdx.x;
    const int w    = t >> 5;
    const int lane = t & 31;
    const int g    = lane >> 2;
    const int tig  = lane & 3;
    const int qh   = w >> 3;               // 0/1: 16-row half
    const int n0   = (w & 7) * 8;          // k-col group within tile
    const int ra   = qh * 16 + g;
    const int rb   = ra + 8;

    const int bh = blockIdx.x >> 6;        // 64 q-tiles per (b,h)
    const int qt = blockIdx.x & 63;
    const int b  = bh >> 2;
    const int h  = bh & 3;
    const int q0 = qt * TQ;

    const __half* Qg = g_Qeh + ((size_t)bh * SEQ + q0) * 128;
    const __half* Kg = g_Keh + (size_t)bh * SEQ * 128;
    const __half* Vg = g_Veh + (size_t)bh * 64 * SEQ;
    const unsigned* Mb = g_maskb + ((size_t)b * SEQ + q0) * 64;
    __half* php = g_ph + ((size_t)bh * SEQ + q0) * SEQ;
    float* ao = attn_out + ((size_t)bh * SEQ + q0) * SEQ;

    // ---- stage Q + tile 0 ----
    for (int i = t; i < TQ * 16; i += 512) {
        int r = i >> 4, c8 = (i & 15) * 8;
        cp_async16(qs + r * KH + c8, Qg + (size_t)r * 128 + c8);
    }
    for (int i = t; i < 64 * 16; i += 512) {
        int r = i >> 4, c8 = (i & 15) * 8;
        cp_async16(ks + r * KH + c8, Kg + (size_t)r * 128 + c8);
    }
    for (int i = t; i < 64 * 8; i += 512) {
        int r = i >> 3, c8 = (i & 7) * 8;
        cp_async16(vsh + r * VH + c8, Vg + (size_t)r * SEQ + c8);
    }
    if (t < 2 * TQ)
        cp_async4(msb + t, Mb + (size_t)(t >> 1) * 64 + (t & 1));
    CP_COMMIT();
    CP_WAIT(0);
    __syncthreads();

    // ---- hoist A (Q) fragments: 8 k16-chunks x 4 regs ----
    unsigned a[8][4];
    #pragma unroll
    for (int kk = 0; kk < 8; ++kk) {
        a[kk][0] = *(const unsigned*)(qs + ra * KH + kk * 16 + 2 * tig);
        a[kk][1] = *(const unsigned*)(qs + rb * KH + kk * 16 + 2 * tig);
        a[kk][2] = *(const unsigned*)(qs + ra * KH + kk * 16 + 2 * tig + 8);
        a[kk][3] = *(const unsigned*)(qs + rb * KH + kk * 16 + 2 * tig + 8);
    }

    float ctx0 = 0.f, ctx1 = 0.f, ctx2 = 0.f, ctx3 = 0.f;
    float sl0 = 0.f, sl1 = 0.f;
    const int col = n0 + 2 * tig;

    for (int tile = 0; tile < SEQ / 64; ++tile) {
        const int buf = tile & 1;
        const __half* kb = ks  + buf * 64 * KH;
        const __half* vb = vsh + buf * 64 * VH;
        const __half* pb = psh + buf * TQ * VH;
        const unsigned* mb = msb + buf * 2 * TQ;
        const int k0 = tile * 64;

        // ---- prefetch tile+1 ----
        if (tile + 1 < SEQ / 64) {
            const int nb = buf ^ 1;
            const int nk0 = k0 + 64;
            for (int i = t; i < 64 * 16; i += 512) {
                int r = i >> 4, c8 = (i & 15) * 8;
                cp_async16(ks + nb * 64 * KH + r * KH + c8,
                           Kg + (size_t)(nk0 + r) * 128 + c8);
            }
            for (int i = t; i < 64 * 8; i += 512) {
                int r = i >> 3, c8 = (i & 7) * 8;
                cp_async16(vsh + nb * 64 * VH + r * VH + c8,
                           Vg + (size_t)r * SEQ + nk0 + c8);
            }
            if (t < 2 * TQ)
                cp_async4(msb + nb * 2 * TQ + t,
                          Mb + (size_t)(t >> 1) * 64 + (nk0 >> 5) + (t & 1));
            CP_COMMIT();
        }

        // ---- QK scores: 8 fp16 k16 mmas ----
        float c0 = 0.f, c1 = 0.f, c2 = 0.f, c3 = 0.f;
        #pragma unroll
        for (int kk = 0; kk < 8; ++kk) {
            unsigned b0 = *(const unsigned*)(kb + (n0 + g) * KH + kk * 16 + 2 * tig);
            unsigned b1 = *(const unsigned*)(kb + (n0 + g) * KH + kk * 16 + 2 * tig + 8);
            mma_f16_k16(c0, c1, c2, c3, a[kk][0], a[kk][1], a[kk][2], a[kk][3], b0, b1);
        }

        // ---- mask + exp ----
        unsigned w0 = mb[ra * 2 + (col >> 5)];
        unsigned w1 = mb[rb * 2 + (col >> 5)];
        float p00 = ((w0 >> (col & 31)) & 1u)       ? 0.f : __expf(c0);
        float p01 = ((w0 >> ((col + 1) & 31)) & 1u) ? 0.f : __expf(c1);
        float p10 = ((w1 >> (col & 31)) & 1u)       ? 0.f : __expf(c2);
        float p11 = ((w1 >> ((col + 1) & 31)) & 1u) ? 0.f : __expf(c3);
        sl0 += p00 + p01;
        sl1 += p10 + p11;

        // ---- p fp16: scratch global + psh (same packed value) ----
        __half2 hp0 = __floats2half2_rn(p00, p01);
        __half2 hp1 = __floats2half2_rn(p10, p11);
        *(__half2*)(php + (size_t)ra * SEQ + k0 + col) = hp0;
        *(__half2*)(php + (size_t)rb * SEQ + k0 + col) = hp1;
        *(__half2*)(psh + buf * TQ * VH + ra * VH + col) = hp0;
        *(__half2*)(psh + buf * TQ * VH + rb * VH + col) = hp1;
        __syncthreads();    // S1: psh complete

        // ---- fp16 PV: 4 k16 mmas ----
        #pragma unroll
        for (int kk = 0; kk < 4; ++kk) {
            unsigned pa0 = *(const unsigned*)(pb + ra * VH + kk * 16 + 2 * tig);
            unsigned pa1 = *(const unsigned*)(pb + rb * VH + kk * 16 + 2 * tig);
            unsigned pa2 = *(const unsigned*)(pb + ra * VH + kk * 16 + 2 * tig + 8);
            unsigned pa3 = *(const unsigned*)(pb + rb * VH + kk * 16 + 2 * tig + 8);
            unsigned vb0 = *(const unsigned*)(vb + (n0 + g) * VH + kk * 16 + 2 * tig);
            unsigned vb1 = *(const unsigned*)(vb + (n0 + g) * VH + kk * 16 + 2 * tig + 8);
            mma_f16_k16(ctx0, ctx1, ctx2, ctx3, pa0, pa1, pa2, pa3, vb0, vb1);
        }

        CP_WAIT(0);
        __syncthreads();    // S2: next tile visible; buffers free
    }

    // ---- row-sum reduction ----
    sl0 += __shfl_xor_sync(0xffffffffu, sl0, 1);
    sl0 += __shfl_xor_sync(0xffffffffu, sl0, 2);
    sl1 += __shfl_xor_sync(0xffffffffu, sl1, 1);
    sl1 += __shfl_xor_sync(0xffffffffu, sl1, 2);
    if (tig == 0) {
        red[w * 16 + g]     = sl0;
        red[w * 16 + 8 + g] = sl1;
    }
    __syncthreads();
    if (t < TQ) {
        int qh_r = t >> 4;
        int rr   = t & 15;
        float s = 0.f;
        #pragma unroll
        for (int ww = 0; ww < 8; ++ww) s += red[(qh_r * 8 + ww) * 16 + rr];
        inv[t] = 1.f / s;
    }
    __syncthreads();

    // ---- normalized ctx write ----
    {
        float iv0 = inv[ra];
        float iv1 = inv[rb];
        size_t r0 = (size_t)b * SEQ + q0;
        *(float2*)(g_ctx + (r0 + ra) * 256 + h * 64 + col) = make_float2(ctx0 * iv0, ctx1 * iv0);
        *(float2*)(g_ctx + (r0 + rb) * 256 + h * 64 + col) = make_float2(ctx2 * iv1, ctx3 * iv1);
    }

    // ---- normalize: read fp16 scratch (L2-warm), write fp32 attn once ----
    for (int r = 0; r < TQ; ++r) {
        float iv = inv[r];
        const __half2* src = (const __half2*)(php + (size_t)r * SEQ) + t * 2;
        __half2 h0 = src[0];
        __half2 h1 = src[1];
        float2 f0 = __half22float2(h0);
        float2 f1 = __half22float2(h1);
        float4 v;
        v.x = f0.x * iv; v.y = f0.y * iv; v.z = f1.x * iv; v.w = f1.y * iv;
        *((float4*)(ao + (size_t)r * SEQ) + t) = v;
    }
}

// ---------------------------------------------------------------------------
// Kernel 3: fc + LN1 + FFN + LN2 (unchanged)
// ---------------------------------------------------------------------------
#define POST_SMEM_BYTES ((64*260 + 256*68 + 4*64*68) * 4)

__global__ void __launch_bounds__(256) post_kernel(
    const float* __restrict__ x, const float* __restrict__ fcw,
    const float* __restrict__ ln1g, const float* __restrict__ ln1b,
    const float* __restrict__ f1, const float* __restrict__ f2,
    const float* __restrict__ ln2g, const float* __restrict__ ln2b,
    float* __restrict__ res) {
    extern __shared__ float sm[];
    float* cs  = sm;                 // 64 x 260
    float* fs  = cs + 64 * 260;      // 256 x 68
    float* hs  = fs + 256 * 68;      // 64 x 68
    float* es  = hs + 64 * 68;       // 64 x 68
    float* f1s = es + 64 * 68;       // 64 x 68
    float* f2s = f1s + 64 * 68;      // 64 x 68

    const int t = threadIdx.x;
    const int row0 = blockIdx.x * 64;

    for (int i = t; i < 64 * 64; i += 256) {
        int r = i >> 6, c = (i & 63) * 4;
        *(float4*)(cs + r * 260 + c) = *(const float4*)(g_ctx + (size_t)(row0 + r) * 256 + c);
    }
    for (int i = t; i < 256 * 16; i += 256) {
        int r = i >> 4, c = (i & 15) * 4;
        *(float4*)(fs + r * 68 + c) = *(const float4*)(fcw + r * 64 + c);
    }
    for (int i = t; i < 64 * 16; i += 256) {
        int r = i >> 4, c = (i & 15) * 4;
        *(float4*)(hs + r * 68 + c)  = *(const float4*)(x + (size_t)(row0 + r) * DM + c);
        *(float4*)(f1s + r * 68 + c) = *(const float4*)(f1 + r * 64 + c);
        *(float4*)(f2s + r * 68 + c) = *(const float4*)(f2 + r * 64 + c);
    }
    __syncthreads();

    const int rg = t >> 4;
    const int cg = t & 15;

    float acc[4][4];
    #pragma unroll
    for (int i = 0; i < 4; ++i)
        #pragma unroll
        for (int j = 0; j < 4; ++j) acc[i][j] = 0.f;
    for (int k = 0; k < 256; ++k) {
        float av[4];
        #pragma unroll
        for (int i = 0; i < 4; ++i) av[i] = cs[(rg * 4 + i) * 260 + k];
        float4 bb = *(const float4*)(fs + k * 68 + cg * 4);
        float bv[4] = {bb.x, bb.y, bb.z, bb.w};
        #pragma unroll
        for (int i = 0; i < 4; ++i)
            #pragma unroll
            for (int j = 0; j < 4; ++j) acc[i][j] += av[i] * bv[j];
    }

    #pragma unroll
    for (int i = 0; i < 4; ++i) {
        float y[4];
        #pragma unroll
        for (int j = 0; j < 4; ++j) y[j] = acc[i][j] + hs[(rg * 4 + i) * 68 + cg * 4 + j];
        float s = y[0] + y[1] + y[2] + y[3];
        float q = y[0]*y[0] + y[1]*y[1] + y[2]*y[2] + y[3]*y[3];
        #pragma unroll
        for (int o = 1; o < 16; o <<= 1) {
            s += __shfl_xor_sync(0xffffffffu, s, o);
            q += __shfl_xor_sync(0xffffffffu, q, o);
        }
        float mu = s * (1.f / 64.f);
        float var = q * (1.f / 64.f) - mu * mu;
        float rs = rsqrtf(var + 1e-5f);
        #pragma unroll
        for (int j = 0; j < 4; ++j) {
            int c = cg * 4 + j;
            es[(rg * 4 + i) * 68 + c] = (y[j] - mu) * rs * ln1g[c] + ln1b[c];
        }
    }
    __syncthreads();

    float h4[4][4];
    #pragma unroll
    for (int i = 0; i < 4; ++i)
        #pragma unroll
        for (int j = 0; j < 4; ++j) h4[i][j] = 0.f;
    for (int k = 0; k < 64; ++k) {
        float av[4];
        #pragma unroll
        for (int i = 0; i < 4; ++i) av[i] = es[(rg * 4 + i) * 68 + k];
        float4 bb = *(const float4*)(f1s + k * 68 + cg * 4);
        float bv[4] = {bb.x, bb.y, bb.z, bb.w};
        #pragma unroll
        for (int i = 0; i < 4; ++i)
            #pragma unroll
            for (int j = 0; j < 4; ++j) h4[i][j] += av[i] * bv[j];
    }
    #pragma unroll
    for (int i = 0; i < 4; ++i)
        #pragma unroll
        for (int j = 0; j < 4; ++j)
            hs[(rg * 4 + i) * 68 + cg * 4 + j] = fmaxf(h4[i][j], 0.f);
    __syncthreads();

    float fa[4][4];
    #pragma unroll
    for (int i = 0; i < 4; ++i)
        #pragma unroll
        for (int j = 0; j < 4; ++j) fa[i][j] = 0.f;
    for (int k = 0; k < 64; ++k) {
        float av[4];
        #pragma unroll
        for (int i = 0; i < 4; ++i) av[i] = hs[(rg * 4 + i) * 68 + k];
        float4 bb = *(const float4*)(f2s + k * 68 + cg * 4);
        float bv[4] = {bb.x, bb.y, bb.z, bb.w};
        #pragma unroll
        for (int i = 0; i < 4; ++i)
            #pragma unroll
            for (int j = 0; j < 4; ++j) fa[i][j] += av[i] * bv[j];
    }
    #pragma unroll
    for (int i = 0; i < 4; ++i) {
        float y[4];
        #pragma unroll
        for (int j = 0; j < 4; ++j) y[j] = fa[i][j] + es[(rg * 4 + i) * 68 + cg * 4 + j];
        float s = y[0] + y[1] + y[2] + y[3];
        float q = y[0]*y[0] + y[1]*y[1] + y[2]*y[2] + y[3]*y[3];
        #pragma unroll
        for (int o = 1; o < 16; o <<= 1) {
            s += __shfl_xor_sync(0xffffffffu, s, o);
            q += __shfl_xor_sync(0xffffffffu, q, o);
        }
        float mu = s * (1.f / 64.f);
        float var = q * (1.f / 64.f) - mu * mu;
        float rs = rsqrtf(var + 1e-5f);
        float4 o4;
        o4.x = (y[0] - mu) * rs * ln2g[cg * 4 + 0] + ln2b[cg * 4 + 0];
        o4.y = (y[1] - mu) * rs * ln2g[cg * 4 + 1] + ln2b[cg * 4 + 1];
        o4.z = (y[2] - mu) * rs * ln2g[cg * 4 + 2] + ln2b[cg * 4 + 2];
        o4.w = (y[3] - mu) * rs * ln2g[cg * 4 + 3] + ln2b[cg * 4 + 3];
        *(float4*)(res + (size_t)(row0 + rg * 4 + i) * 64 + cg * 4) = o4;
    }
}

// ---------------------------------------------------------------------------
// Launch
// ---------------------------------------------------------------------------
extern "C" void kernel_launch(void* const* d_in, const int* in_sizes, int n_in,
                              void* d_out, int out_size) {
    const float* x    = (const float*)d_in[0];
    const void*  mask = d_in[1];
    const float* u    = (const float*)d_in[2];
    const float* wq   = (const float*)d_in[3];
    const float* wk   = (const float*)d_in[4];
    const float* wv   = (const float*)d_in[5];
    const float* uqw  = (const float*)d_in[6];
    const float* ukw  = (const float*)d_in[7];
    const float* uvw  = (const float*)d_in[8];
    const float* sq1  = (const float*)d_in[9];
    const float* sq2  = (const float*)d_in[10];
    const float* sk1  = (const float*)d_in[11];
    const float* sk2  = (const float*)d_in[12];
    const float* sv1  = (const float*)d_in[13];
    const float* sv2  = (const float*)d_in[14];
    const float* fcw  = (const float*)d_in[15];
    const float* ln1g = (const float*)d_in[16];
    const float* ln1b = (const float*)d_in[17];
    const float* ffn1 = (const float*)d_in[18];
    const float* ffn2 = (const float*)d_in[19];
    const float* ln2g = (const float*)d_in[20];
    const float* ln2b = (const float*)d_in[21];

    float* res  = (float*)d_out;
    float* attn = res + (size_t)NB * SEQ * DM;

    cudaFuncSetAttribute(proj_kernel,  cudaFuncAttributeMaxDynamicSharedMemorySize, PROJ_SMEM_BYTES);
    cudaFuncSetAttribute(attn2_kernel, cudaFuncAttributeMaxDynamicSharedMemorySize, ATT_SMEM_BYTES);
    cudaFuncSetAttribute(post_kernel,  cudaFuncAttributeMaxDynamicSharedMemorySize, POST_SMEM_BYTES);

    detect_mask_kernel<<<1, 32>>>((const unsigned char*)mask);
    convert_mask_kernel<<<(NB * SEQ * SEQ) / 256, 256>>>(mask);
    gates_kernel<<<NB, 32>>>(u, sq1, sq2, sk1, sk2, sv1, sv2);
    proj_kernel<<<(NB * SEQ) / 64, 256, PROJ_SMEM_BYTES>>>(x, wq, wk, wv, uqw, ukw, uvw);
    transpose_v_kernel<<<NB * NH * 32, 256>>>();
    attn2_kernel<<<NB * NH * (SEQ / TQ), 512, ATT_SMEM_BYTES>>>(attn);
    post_kernel<<<(NB * SEQ) / 64, 256, POST_SMEM_BYTES>>>(x, fcw, ln1g, ln1b, ffn1, ffn2,
                                                           ln2g, ln2b, res);
}